// round 1
// baseline (speedup 1.0000x reference)
#include <cuda_runtime.h>

#define Bq 4
#define Sq 2048
#define Dq 1024
#define Hq 16
#define HDq 64
#define BSq (Bq*Sq)   // 8192

// Scratch (allocation-free rule: __device__ globals)
__device__ float g_Q[BSq*Dq];
__device__ float g_K[BSq*Dq];
__device__ float g_V[BSq*Dq];
__device__ float g_A[BSq*Dq];

// ---------------------------------------------------------------------------
// C[m][n] = sum_k A[m][k] * W[n][k] + bias[n]     (torch Linear: x @ W^T + b)
// Tile 128x128, K-step 8, 256 threads, 8x8 per-thread register tile.
// ---------------------------------------------------------------------------
__global__ __launch_bounds__(256, 2)
void gemm_bias_kernel(const float* __restrict__ A, const float* __restrict__ W,
                      const float* __restrict__ bias, float* __restrict__ C,
                      int M, int N, int K)
{
    __shared__ float sA[8][128];
    __shared__ float sB[8][128];

    const int tid = threadIdx.x;
    const int m0 = blockIdx.y * 128;
    const int n0 = blockIdx.x * 128;

    const int lr  = tid >> 1;        // 0..127 row within tile
    const int lkq = tid & 1;         // which half of the 8 k's

    const float* Aptr = A + (size_t)(m0 + lr) * K + lkq * 4;
    const float* Wptr = W + (size_t)(n0 + lr) * K + lkq * 4;

    const int tr = tid >> 4;         // 0..15 -> rows tr*8..tr*8+7
    const int tc = tid & 15;         // 0..15 -> cols tc*8..tc*8+7

    float acc[8][8];
    #pragma unroll
    for (int i = 0; i < 8; i++)
        #pragma unroll
        for (int j = 0; j < 8; j++) acc[i][j] = 0.f;

    for (int k0 = 0; k0 < K; k0 += 8) {
        float4 av = *(const float4*)(Aptr + k0);
        float4 wv = *(const float4*)(Wptr + k0);
        __syncthreads();
        sA[lkq*4+0][lr] = av.x; sA[lkq*4+1][lr] = av.y;
        sA[lkq*4+2][lr] = av.z; sA[lkq*4+3][lr] = av.w;
        sB[lkq*4+0][lr] = wv.x; sB[lkq*4+1][lr] = wv.y;
        sB[lkq*4+2][lr] = wv.z; sB[lkq*4+3][lr] = wv.w;
        __syncthreads();

        #pragma unroll
        for (int kk = 0; kk < 8; kk++) {
            float a[8], b[8];
            *(float4*)(a)     = *(const float4*)&sA[kk][tr*8];
            *(float4*)(a + 4) = *(const float4*)&sA[kk][tr*8 + 4];
            *(float4*)(b)     = *(const float4*)&sB[kk][tc*8];
            *(float4*)(b + 4) = *(const float4*)&sB[kk][tc*8 + 4];
            #pragma unroll
            for (int i = 0; i < 8; i++)
                #pragma unroll
                for (int j = 0; j < 8; j++)
                    acc[i][j] += a[i] * b[j];
        }
    }

    float4 b0 = *(const float4*)&bias[n0 + tc*8];
    float4 b1 = *(const float4*)&bias[n0 + tc*8 + 4];
    #pragma unroll
    for (int i = 0; i < 8; i++) {
        float* Crow = C + (size_t)(m0 + tr*8 + i) * N + n0 + tc*8;
        float4 r0, r1;
        r0.x = acc[i][0] + b0.x; r0.y = acc[i][1] + b0.y;
        r0.z = acc[i][2] + b0.z; r0.w = acc[i][3] + b0.w;
        r1.x = acc[i][4] + b1.x; r1.y = acc[i][5] + b1.y;
        r1.z = acc[i][6] + b1.z; r1.w = acc[i][7] + b1.w;
        *(float4*)(Crow)     = r0;
        *(float4*)(Crow + 4) = r1;
    }
}

// ---------------------------------------------------------------------------
// Flash attention (fp32, online softmax).
// CTA: 64 queries x one (b,h). 256 threads. K/V streamed in 64-key tiles.
// smem: sQt[d][row], sKt[d][key] (reused as sPt[key][row]), sV[key][d],
//       sS[row][key] stride 68, plus m/l/corr rows.
// ---------------------------------------------------------------------------
#define ATT_SMEM_FLOATS (3*64*64 + 64*68 + 3*64)
#define ATT_SMEM_BYTES  (ATT_SMEM_FLOATS * 4)

__global__ __launch_bounds__(256)
void attn_kernel(const float* __restrict__ Q, const float* __restrict__ K,
                 const float* __restrict__ V, float* __restrict__ O)
{
    extern __shared__ float smem[];
    float* sQt = smem;                 // 64*64, [d][row]
    float* sKt = sQt + 64*64;          // 64*64, [d][key]; reused as sPt[key][row]
    float* sV  = sKt + 64*64;          // 64*64, [key][d]
    float* sS  = sV  + 64*64;          // 64*68, [row][*] stride 68
    float* s_m = sS  + 64*68;          // 64
    float* s_l = s_m + 64;             // 64
    float* s_c = s_l + 64;             // 64

    const int tid = threadIdx.x;
    const int bh  = blockIdx.y;
    const int b   = bh >> 4;
    const int h   = bh & 15;
    const int q0  = blockIdx.x * 64;

    const float* Qbase = Q + ((size_t)(b*Sq) + q0) * Dq + h * HDq;
    const float* Kbase = K + (size_t)(b*Sq) * Dq + h * HDq;
    const float* Vbase = V + (size_t)(b*Sq) * Dq + h * HDq;

    // Load Q block transposed: sQt[d][row]
    #pragma unroll
    for (int i = 0; i < 4; i++) {
        int idx = tid + i * 256;
        int row = idx >> 4;
        int dq  = (idx & 15) * 4;
        float4 qv = *(const float4*)(Qbase + (size_t)row * Dq + dq);
        sQt[(dq+0)*64 + row] = qv.x;
        sQt[(dq+1)*64 + row] = qv.y;
        sQt[(dq+2)*64 + row] = qv.z;
        sQt[(dq+3)*64 + row] = qv.w;
    }
    if (tid < 64) { s_m[tid] = -1e30f; s_l[tid] = 0.f; }

    const int tr = tid >> 4, tc = tid & 15;
    const int r4 = tr * 4, c4 = tc * 4;

    float o[4][4];
    #pragma unroll
    for (int i = 0; i < 4; i++)
        #pragma unroll
        for (int j = 0; j < 4; j++) o[i][j] = 0.f;

    for (int t = 0; t < Sq/64; t++) {
        __syncthreads();  // prior O-gemm (reads sKt-as-sPt, sV) complete
        const float* Kb = Kbase + (size_t)t * 64 * Dq;
        const float* Vb = Vbase + (size_t)t * 64 * Dq;
        #pragma unroll
        for (int i = 0; i < 4; i++) {
            int idx = tid + i * 256;
            int key = idx >> 4;
            int dq  = (idx & 15) * 4;
            float4 kv = *(const float4*)(Kb + (size_t)key * Dq + dq);
            sKt[(dq+0)*64 + key] = kv.x;
            sKt[(dq+1)*64 + key] = kv.y;
            sKt[(dq+2)*64 + key] = kv.z;
            sKt[(dq+3)*64 + key] = kv.w;
            float4 vv = *(const float4*)(Vb + (size_t)key * Dq + dq);
            *(float4*)&sV[key*64 + dq] = vv;
        }
        __syncthreads();

        // S = Q K^T (scaled)
        float s[4][4];
        #pragma unroll
        for (int i = 0; i < 4; i++)
            #pragma unroll
            for (int j = 0; j < 4; j++) s[i][j] = 0.f;
        #pragma unroll
        for (int d = 0; d < 64; d++) {
            float a[4], bv[4];
            *(float4*)a  = *(const float4*)&sQt[d*64 + r4];
            *(float4*)bv = *(const float4*)&sKt[d*64 + c4];
            #pragma unroll
            for (int i = 0; i < 4; i++)
                #pragma unroll
                for (int j = 0; j < 4; j++)
                    s[i][j] += a[i] * bv[j];
        }
        #pragma unroll
        for (int i = 0; i < 4; i++) {
            float4 w;
            w.x = s[i][0]*0.125f; w.y = s[i][1]*0.125f;
            w.z = s[i][2]*0.125f; w.w = s[i][3]*0.125f;
            *(float4*)&sS[(r4+i)*68 + c4] = w;
        }
        __syncthreads();

        // Online softmax: 4 lanes per row
        {
            int r = tid >> 2, part = tid & 3;
            const float* rowp = &sS[r*68 + part*16];
            float vbuf[16];
            float mx = -1e30f;
            #pragma unroll
            for (int j = 0; j < 16; j++) { vbuf[j] = rowp[j]; mx = fmaxf(mx, vbuf[j]); }
            mx = fmaxf(mx, __shfl_xor_sync(0xffffffffu, mx, 1));
            mx = fmaxf(mx, __shfl_xor_sync(0xffffffffu, mx, 2));
            float mold = s_m[r];
            float mnew = fmaxf(mold, mx);
            float corr = __expf(mold - mnew);
            float lsum = 0.f;
            #pragma unroll
            for (int j = 0; j < 16; j++) {
                float p = __expf(vbuf[j] - mnew);
                lsum += p;
                vbuf[j] = p;
            }
            // write P transposed into sPt (= sKt region): sPt[key][row]
            #pragma unroll
            for (int j = 0; j < 16; j++)
                sKt[(part*16 + j)*64 + r] = vbuf[j];
            lsum += __shfl_xor_sync(0xffffffffu, lsum, 1);
            lsum += __shfl_xor_sync(0xffffffffu, lsum, 2);
            if (part == 0) {
                s_m[r] = mnew;
                s_l[r] = s_l[r] * corr + lsum;
                s_c[r] = corr;
            }
        }
        __syncthreads();

        // O = O*corr + P V
        float cr[4];
        #pragma unroll
        for (int i = 0; i < 4; i++) cr[i] = s_c[r4+i];
        #pragma unroll
        for (int i = 0; i < 4; i++)
            #pragma unroll
            for (int j = 0; j < 4; j++) o[i][j] *= cr[i];
        #pragma unroll
        for (int kk = 0; kk < 64; kk++) {
            float a[4], bv[4];
            *(float4*)a  = *(const float4*)&sKt[kk*64 + r4];   // P
            *(float4*)bv = *(const float4*)&sV[kk*64 + c4];
            #pragma unroll
            for (int i = 0; i < 4; i++)
                #pragma unroll
                for (int j = 0; j < 4; j++)
                    o[i][j] += a[i] * bv[j];
        }
    }

    // Epilogue: divide by l, write out
    float* Obase = O + ((size_t)(b*Sq) + q0) * Dq + h * HDq;
    #pragma unroll
    for (int i = 0; i < 4; i++) {
        float inv = 1.f / s_l[r4+i];
        float4 w;
        w.x = o[i][0]*inv; w.y = o[i][1]*inv;
        w.z = o[i][2]*inv; w.w = o[i][3]*inv;
        *(float4*)(Obase + (size_t)(r4+i)*Dq + c4) = w;
    }
}

// ---------------------------------------------------------------------------
extern "C" void kernel_launch(void* const* d_in, const int* in_sizes, int n_in,
                              void* d_out, int out_size)
{
    const float* q   = (const float*)d_in[0];
    const float* k   = (const float*)d_in[1];
    const float* v   = (const float*)d_in[2];
    const float* w_q = (const float*)d_in[3];
    const float* b_q = (const float*)d_in[4];
    const float* w_k = (const float*)d_in[5];
    const float* b_k = (const float*)d_in[6];
    const float* w_v = (const float*)d_in[7];
    const float* b_v = (const float*)d_in[8];
    const float* w_fc= (const float*)d_in[9];
    const float* b_fc= (const float*)d_in[10];
    float* out = (float*)d_out;

    float *gQ, *gK, *gV, *gA;
    cudaGetSymbolAddress((void**)&gQ, g_Q);
    cudaGetSymbolAddress((void**)&gK, g_K);
    cudaGetSymbolAddress((void**)&gV, g_V);
    cudaGetSymbolAddress((void**)&gA, g_A);

    cudaFuncSetAttribute(attn_kernel,
                         cudaFuncAttributeMaxDynamicSharedMemorySize,
                         ATT_SMEM_BYTES);

    dim3 gblk(256);
    dim3 ggrid(Dq/128, BSq/128);   // 8 x 64

    gemm_bias_kernel<<<ggrid, gblk>>>(q, w_q, b_q, gQ, BSq, Dq, Dq);
    gemm_bias_kernel<<<ggrid, gblk>>>(k, w_k, b_k, gK, BSq, Dq, Dq);
    gemm_bias_kernel<<<ggrid, gblk>>>(v, w_v, b_v, gV, BSq, Dq, Dq);

    attn_kernel<<<dim3(Sq/64, Bq*Hq), 256, ATT_SMEM_BYTES>>>(gQ, gK, gV, gA);

    gemm_bias_kernel<<<ggrid, gblk>>>(gA, w_fc, b_fc, out, BSq, Dq, Dq);
}

// round 3
// speedup vs baseline: 1.3673x; 1.3673x over previous
#include <cuda_runtime.h>
#include <cuda_bf16.h>
#include <cstdint>

#define Bq 4
#define Sq 2048
#define Dq 1024
#define Hq 16
#define HDq 64
#define BSq (Bq*Sq)   // 8192
#define DD  (Dq*Dq)

// ---------------- scratch (__device__ globals; no allocs allowed) ----------
__device__ float g_Q[BSq*Dq];
__device__ float g_K[BSq*Dq];
__device__ float g_V[BSq*Dq];
__device__ float g_A[BSq*Dq];
__device__ __nv_bfloat16 g_xh[BSq*Dq];
__device__ __nv_bfloat16 g_xl[BSq*Dq];
__device__ __nv_bfloat16 g_wh[4*DD];
__device__ __nv_bfloat16 g_wl[4*DD];

__device__ __forceinline__ uint32_t smem_to_u32(const void* p) {
    uint32_t a;
    asm("{ .reg .u64 t; cvta.to.shared.u64 t, %1; cvt.u32.u64 %0, t; }"
        : "=r"(a) : "l"(p));
    return a;
}

__device__ __forceinline__ void cp16(uint32_t dst, const void* src) {
    asm volatile("cp.async.cg.shared.global [%0], [%1], 16;"
                 :: "r"(dst), "l"(src) : "memory");
}
__device__ __forceinline__ void cp_commit() {
    asm volatile("cp.async.commit_group;" ::: "memory");
}
template <int N>
__device__ __forceinline__ void cp_wait() {
    asm volatile("cp.async.wait_group %0;" :: "n"(N) : "memory");
}

__device__ __forceinline__ void ldsm_x4(uint32_t* r, uint32_t addr) {
    asm volatile("ldmatrix.sync.aligned.m8n8.x4.shared.b16 {%0,%1,%2,%3}, [%4];"
                 : "=r"(r[0]), "=r"(r[1]), "=r"(r[2]), "=r"(r[3]) : "r"(addr));
}

__device__ __forceinline__ void mma_bf16(float* d, const uint32_t* a, const uint32_t* b) {
    asm volatile(
        "mma.sync.aligned.m16n8k16.row.col.f32.bf16.bf16.f32 "
        "{%0,%1,%2,%3}, {%4,%5,%6,%7}, {%8,%9}, {%0,%1,%2,%3};"
        : "+f"(d[0]), "+f"(d[1]), "+f"(d[2]), "+f"(d[3])
        : "r"(a[0]), "r"(a[1]), "r"(a[2]), "r"(a[3]), "r"(b[0]), "r"(b[1]));
}

// ---------------------------------------------------------------------------
// fp32 -> (bf16 hi, bf16 lo) split
// ---------------------------------------------------------------------------
__global__ void split_kernel(const float4* __restrict__ x,
                             __nv_bfloat162* __restrict__ hi,
                             __nv_bfloat162* __restrict__ lo, int n4)
{
    int i = blockIdx.x * blockDim.x + threadIdx.x;
    if (i >= n4) return;
    float4 v = x[i];
    __nv_bfloat16 h0 = __float2bfloat16(v.x);
    __nv_bfloat16 h1 = __float2bfloat16(v.y);
    __nv_bfloat16 h2 = __float2bfloat16(v.z);
    __nv_bfloat16 h3 = __float2bfloat16(v.w);
    __nv_bfloat16 l0 = __float2bfloat16(v.x - __bfloat162float(h0));
    __nv_bfloat16 l1 = __float2bfloat16(v.y - __bfloat162float(h1));
    __nv_bfloat16 l2 = __float2bfloat16(v.z - __bfloat162float(h2));
    __nv_bfloat16 l3 = __float2bfloat16(v.w - __bfloat162float(h3));
    hi[i*2 + 0] = __nv_bfloat162(h0, h1);
    hi[i*2 + 1] = __nv_bfloat162(h2, h3);
    lo[i*2 + 0] = __nv_bfloat162(l0, l1);
    lo[i*2 + 1] = __nv_bfloat162(l2, l3);
}

// ---------------------------------------------------------------------------
// HMMA split-GEMM: C[m][n] = (Ah+Al)[m][:] . (Wh+Wl)[n][:] + bias[n]
// CTA 128x128, 8 warps (warp tile 64x32), K-chunk 32, 2-stage cp.async.
// smem per stage: 4 matrices x 128 rows x 40 bf16 (pad) = 40960 B
// ---------------------------------------------------------------------------
#define GSTRIDE 40                       // padded bf16 row stride
#define GMAT    (128*GSTRIDE*2)          // 10240 B per matrix buffer
#define GSTAGE  (4*GMAT)                 // 40960 B per stage
#define GSMEM   (2*GSTAGE)               // 81920 B total
#define NCHUNK  (Dq/32)                  // 32

__global__ __launch_bounds__(256, 2)
void gemm_mma_kernel(const __nv_bfloat16* __restrict__ Ah,
                     const __nv_bfloat16* __restrict__ Al,
                     const __nv_bfloat16* __restrict__ Wh,
                     const __nv_bfloat16* __restrict__ Wl,
                     const float* __restrict__ bias, float* __restrict__ C)
{
    extern __shared__ char smem[];
    const uint32_t smem_base = smem_to_u32(smem);
    const int tid  = threadIdx.x;
    const int lane = tid & 31;
    const int wid  = tid >> 5;
    const int m0 = blockIdx.y * 128;
    const int n0 = blockIdx.x * 128;
    const int wm0 = (wid & 1) * 64;      // warp m-offset in tile
    const int wn0 = (wid >> 1) * 32;     // warp n-offset in tile

    // per-thread cp.async assignments: 512 16B-chunks per matrix, 2 per thread
    const int id0 = tid, id1 = tid + 256;
    const int row0 = id0 >> 2, kq0 = (id0 & 3) * 8;
    const int row1 = id1 >> 2, kq1 = (id1 & 3) * 8;

    const __nv_bfloat16* gAh = Ah + (size_t)m0 * Dq;
    const __nv_bfloat16* gAl = Al + (size_t)m0 * Dq;
    const __nv_bfloat16* gWh = Wh + (size_t)n0 * Dq;
    const __nv_bfloat16* gWl = Wl + (size_t)n0 * Dq;

    float acc[4][4][4];
    #pragma unroll
    for (int i = 0; i < 4; i++)
        #pragma unroll
        for (int j = 0; j < 4; j++)
            #pragma unroll
            for (int r = 0; r < 4; r++) acc[i][j][r] = 0.f;

    auto issue = [&](int c, int s) {
        const int k0 = c * 32;
        uint32_t sb = smem_base + s * GSTAGE;
        uint32_t d0 = (uint32_t)(row0 * (GSTRIDE*2) + kq0 * 2);
        uint32_t d1 = (uint32_t)(row1 * (GSTRIDE*2) + kq1 * 2);
        size_t s0 = (size_t)row0 * Dq + k0 + kq0;
        size_t s1 = (size_t)row1 * Dq + k0 + kq1;
        cp16(sb + 0*GMAT + d0, gAh + s0);
        cp16(sb + 0*GMAT + d1, gAh + s1);
        cp16(sb + 1*GMAT + d0, gAl + s0);
        cp16(sb + 1*GMAT + d1, gAl + s1);
        cp16(sb + 2*GMAT + d0, gWh + s0);
        cp16(sb + 2*GMAT + d1, gWh + s1);
        cp16(sb + 3*GMAT + d0, gWl + s0);
        cp16(sb + 3*GMAT + d1, gWl + s1);
    };

    issue(0, 0);
    cp_commit();

    // ldmatrix per-lane address components
    const int a_r = wm0 + (lane & 15);           // A row within tile
    const int a_c = (lane >> 4) * 8;             // A col offset within k16
    const int b_r = wn0 + (lane & 7) + ((lane >> 4) << 3);  // W row
    const int b_c = ((lane >> 3) & 1) * 8;       // W col offset within k16

    for (int c = 0; c < NCHUNK; c++) {
        const int s = c & 1;
        if (c + 1 < NCHUNK) { issue(c + 1, s ^ 1); cp_commit(); }
        if (c + 1 < NCHUNK) cp_wait<1>(); else cp_wait<0>();
        __syncthreads();

        const uint32_t sb = smem_base + s * GSTAGE;
        const uint32_t aH = sb + 0*GMAT, aL = sb + 1*GMAT;
        const uint32_t wH = sb + 2*GMAT, wL = sb + 3*GMAT;

        #pragma unroll
        for (int kk = 0; kk < 2; kk++) {
            const int k16 = kk * 16;
            // B fragments: 2 x4 loads each for hi/lo cover 4 n-atoms
            uint32_t bh[2][4], bl[2][4];
            #pragma unroll
            for (int jj = 0; jj < 2; jj++) {
                uint32_t off = (uint32_t)((b_r + jj*16) * (GSTRIDE*2) + (k16 + b_c) * 2);
                ldsm_x4(bh[jj], wH + off);
                ldsm_x4(bl[jj], wL + off);
            }
            #pragma unroll
            for (int i = 0; i < 4; i++) {
                uint32_t ah[4], al[4];
                uint32_t off = (uint32_t)((a_r + i*16) * (GSTRIDE*2) + (k16 + a_c) * 2);
                ldsm_x4(ah, aH + off);
                ldsm_x4(al, aL + off);
                #pragma unroll
                for (int j = 0; j < 4; j++) {
                    const uint32_t* bhp = &bh[j >> 1][(j & 1) * 2];
                    const uint32_t* blp = &bl[j >> 1][(j & 1) * 2];
                    mma_bf16(acc[i][j], ah, bhp);
                    mma_bf16(acc[i][j], ah, blp);
                    mma_bf16(acc[i][j], al, bhp);
                }
            }
        }
        __syncthreads();
    }

    // epilogue
    const int g = lane >> 2, t = lane & 3;
    #pragma unroll
    for (int j = 0; j < 4; j++) {
        const int col = n0 + wn0 + j*8 + t*2;
        const float bx = __ldg(&bias[col]);
        const float by = __ldg(&bias[col + 1]);
        #pragma unroll
        for (int i = 0; i < 4; i++) {
            const int r0 = m0 + wm0 + i*16 + g;
            float2 v0, v1;
            v0.x = acc[i][j][0] + bx; v0.y = acc[i][j][1] + by;
            v1.x = acc[i][j][2] + bx; v1.y = acc[i][j][3] + by;
            *(float2*)&C[(size_t)r0 * Dq + col] = v0;
            *(float2*)&C[(size_t)(r0 + 8) * Dq + col] = v1;
        }
    }
}

// ---------------------------------------------------------------------------
// Flash attention (fp32, online softmax) — unchanged from round 1.
// ---------------------------------------------------------------------------
#define ATT_SMEM_FLOATS (3*64*64 + 64*68 + 3*64)
#define ATT_SMEM_BYTES  (ATT_SMEM_FLOATS * 4)

__global__ __launch_bounds__(256)
void attn_kernel(const float* __restrict__ Q, const float* __restrict__ K,
                 const float* __restrict__ V, float* __restrict__ O)
{
    extern __shared__ float fsmem[];
    float* sQt = fsmem;
    float* sKt = sQt + 64*64;
    float* sV  = sKt + 64*64;
    float* sS  = sV  + 64*64;
    float* s_m = sS  + 64*68;
    float* s_l = s_m + 64;
    float* s_c = s_l + 64;

    const int tid = threadIdx.x;
    const int bh  = blockIdx.y;
    const int b   = bh >> 4;
    const int h   = bh & 15;
    const int q0  = blockIdx.x * 64;

    const float* Qbase = Q + ((size_t)(b*Sq) + q0) * Dq + h * HDq;
    const float* Kbase = K + (size_t)(b*Sq) * Dq + h * HDq;
    const float* Vbase = V + (size_t)(b*Sq) * Dq + h * HDq;

    #pragma unroll
    for (int i = 0; i < 4; i++) {
        int idx = tid + i * 256;
        int row = idx >> 4;
        int dq  = (idx & 15) * 4;
        float4 qv = *(const float4*)(Qbase + (size_t)row * Dq + dq);
        sQt[(dq+0)*64 + row] = qv.x;
        sQt[(dq+1)*64 + row] = qv.y;
        sQt[(dq+2)*64 + row] = qv.z;
        sQt[(dq+3)*64 + row] = qv.w;
    }
    if (tid < 64) { s_m[tid] = -1e30f; s_l[tid] = 0.f; }

    const int tr = tid >> 4, tc = tid & 15;
    const int r4 = tr * 4, c4 = tc * 4;

    float o[4][4];
    #pragma unroll
    for (int i = 0; i < 4; i++)
        #pragma unroll
        for (int j = 0; j < 4; j++) o[i][j] = 0.f;

    for (int t = 0; t < Sq/64; t++) {
        __syncthreads();
        const float* Kb = Kbase + (size_t)t * 64 * Dq;
        const float* Vb = Vbase + (size_t)t * 64 * Dq;
        #pragma unroll
        for (int i = 0; i < 4; i++) {
            int idx = tid + i * 256;
            int key = idx >> 4;
            int dq  = (idx & 15) * 4;
            float4 kv = *(const float4*)(Kb + (size_t)key * Dq + dq);
            sKt[(dq+0)*64 + key] = kv.x;
            sKt[(dq+1)*64 + key] = kv.y;
            sKt[(dq+2)*64 + key] = kv.z;
            sKt[(dq+3)*64 + key] = kv.w;
            float4 vv = *(const float4*)(Vb + (size_t)key * Dq + dq);
            *(float4*)&sV[key*64 + dq] = vv;
        }
        __syncthreads();

        float s[4][4];
        #pragma unroll
        for (int i = 0; i < 4; i++)
            #pragma unroll
            for (int j = 0; j < 4; j++) s[i][j] = 0.f;
        #pragma unroll
        for (int d = 0; d < 64; d++) {
            float a[4], bv[4];
            *(float4*)a  = *(const float4*)&sQt[d*64 + r4];
            *(float4*)bv = *(const float4*)&sKt[d*64 + c4];
            #pragma unroll
            for (int i = 0; i < 4; i++)
                #pragma unroll
                for (int j = 0; j < 4; j++)
                    s[i][j] += a[i] * bv[j];
        }
        #pragma unroll
        for (int i = 0; i < 4; i++) {
            float4 w;
            w.x = s[i][0]*0.125f; w.y = s[i][1]*0.125f;
            w.z = s[i][2]*0.125f; w.w = s[i][3]*0.125f;
            *(float4*)&sS[(r4+i)*68 + c4] = w;
        }
        __syncthreads();

        {
            int r = tid >> 2, part = tid & 3;
            const float* rowp = &sS[r*68 + part*16];
            float vbuf[16];
            float mx = -1e30f;
            #pragma unroll
            for (int j = 0; j < 16; j++) { vbuf[j] = rowp[j]; mx = fmaxf(mx, vbuf[j]); }
            mx = fmaxf(mx, __shfl_xor_sync(0xffffffffu, mx, 1));
            mx = fmaxf(mx, __shfl_xor_sync(0xffffffffu, mx, 2));
            float mold = s_m[r];
            float mnew = fmaxf(mold, mx);
            float corr = __expf(mold - mnew);
            float lsum = 0.f;
            #pragma unroll
            for (int j = 0; j < 16; j++) {
                float p = __expf(vbuf[j] - mnew);
                lsum += p;
                vbuf[j] = p;
            }
            #pragma unroll
            for (int j = 0; j < 16; j++)
                sKt[(part*16 + j)*64 + r] = vbuf[j];
            lsum += __shfl_xor_sync(0xffffffffu, lsum, 1);
            lsum += __shfl_xor_sync(0xffffffffu, lsum, 2);
            if (part == 0) {
                s_m[r] = mnew;
                s_l[r] = s_l[r] * corr + lsum;
                s_c[r] = corr;
            }
        }
        __syncthreads();

        float cr[4];
        #pragma unroll
        for (int i = 0; i < 4; i++) cr[i] = s_c[r4+i];
        #pragma unroll
        for (int i = 0; i < 4; i++)
            #pragma unroll
            for (int j = 0; j < 4; j++) o[i][j] *= cr[i];
        #pragma unroll
        for (int kk = 0; kk < 64; kk++) {
            float a[4], bv[4];
            *(float4*)a  = *(const float4*)&sKt[kk*64 + r4];
            *(float4*)bv = *(const float4*)&sV[kk*64 + c4];
            #pragma unroll
            for (int i = 0; i < 4; i++)
                #pragma unroll
                for (int j = 0; j < 4; j++)
                    o[i][j] += a[i] * bv[j];
        }
    }

    float* Obase = O + ((size_t)(b*Sq) + q0) * Dq + h * HDq;
    #pragma unroll
    for (int i = 0; i < 4; i++) {
        float inv = 1.f / s_l[r4+i];
        float4 w;
        w.x = o[i][0]*inv; w.y = o[i][1]*inv;
        w.z = o[i][2]*inv; w.w = o[i][3]*inv;
        *(float4*)(Obase + (size_t)(r4+i)*Dq + c4) = w;
    }
}

// ---------------------------------------------------------------------------
extern "C" void kernel_launch(void* const* d_in, const int* in_sizes, int n_in,
                              void* d_out, int out_size)
{
    const float* q   = (const float*)d_in[0];
    const float* k   = (const float*)d_in[1];
    const float* v   = (const float*)d_in[2];
    const float* w_q = (const float*)d_in[3];
    const float* b_q = (const float*)d_in[4];
    const float* w_k = (const float*)d_in[5];
    const float* b_k = (const float*)d_in[6];
    const float* w_v = (const float*)d_in[7];
    const float* b_v = (const float*)d_in[8];
    const float* w_fc= (const float*)d_in[9];
    const float* b_fc= (const float*)d_in[10];
    float* out = (float*)d_out;

    float *gQ, *gK, *gV, *gA;
    __nv_bfloat16 *xh, *xl, *wh, *wl;
    cudaGetSymbolAddress((void**)&gQ, g_Q);
    cudaGetSymbolAddress((void**)&gK, g_K);
    cudaGetSymbolAddress((void**)&gV, g_V);
    cudaGetSymbolAddress((void**)&gA, g_A);
    cudaGetSymbolAddress((void**)&xh, g_xh);
    cudaGetSymbolAddress((void**)&xl, g_xl);
    cudaGetSymbolAddress((void**)&wh, g_wh);
    cudaGetSymbolAddress((void**)&wl, g_wl);

    cudaFuncSetAttribute(attn_kernel,
                         cudaFuncAttributeMaxDynamicSharedMemorySize, ATT_SMEM_BYTES);
    cudaFuncSetAttribute(gemm_mma_kernel,
                         cudaFuncAttributeMaxDynamicSharedMemorySize, GSMEM);

    const int actN4 = BSq*Dq/4;
    const int wN4   = DD/4;
    dim3 sblk(256);
    dim3 sgrid_act((actN4 + 255)/256);
    dim3 sgrid_w((wN4 + 255)/256);
    dim3 tcgrid(Dq/128, BSq/128);   // 8 x 64

    // weight splits
    split_kernel<<<sgrid_w, sblk>>>((const float4*)w_q,  (__nv_bfloat162*)(wh + 0*DD), (__nv_bfloat162*)(wl + 0*DD), wN4);
    split_kernel<<<sgrid_w, sblk>>>((const float4*)w_k,  (__nv_bfloat162*)(wh + 1*DD), (__nv_bfloat162*)(wl + 1*DD), wN4);
    split_kernel<<<sgrid_w, sblk>>>((const float4*)w_v,  (__nv_bfloat162*)(wh + 2*DD), (__nv_bfloat162*)(wl + 2*DD), wN4);
    split_kernel<<<sgrid_w, sblk>>>((const float4*)w_fc, (__nv_bfloat162*)(wh + 3*DD), (__nv_bfloat162*)(wl + 3*DD), wN4);

    // Q/K/V projections on tensor cores (HMMA)
    split_kernel<<<sgrid_act, sblk>>>((const float4*)q, (__nv_bfloat162*)xh, (__nv_bfloat162*)xl, actN4);
    gemm_mma_kernel<<<tcgrid, 256, GSMEM>>>(xh, xl, wh + 0*DD, wl + 0*DD, b_q, gQ);
    split_kernel<<<sgrid_act, sblk>>>((const float4*)k, (__nv_bfloat162*)xh, (__nv_bfloat162*)xl, actN4);
    gemm_mma_kernel<<<tcgrid, 256, GSMEM>>>(xh, xl, wh + 1*DD, wl + 1*DD, b_k, gK);
    split_kernel<<<sgrid_act, sblk>>>((const float4*)v, (__nv_bfloat162*)xh, (__nv_bfloat162*)xl, actN4);
    gemm_mma_kernel<<<tcgrid, 256, GSMEM>>>(xh, xl, wh + 2*DD, wl + 2*DD, b_v, gV);

    // attention (fp32)
    attn_kernel<<<dim3(Sq/64, Bq*Hq), 256, ATT_SMEM_BYTES>>>(gQ, gK, gV, gA);

    // output projection
    split_kernel<<<sgrid_act, sblk>>>((const float4*)gA, (__nv_bfloat162*)xh, (__nv_bfloat162*)xl, actN4);
    gemm_mma_kernel<<<tcgrid, 256, GSMEM>>>(xh, xl, wh + 3*DD, wl + 3*DD, b_fc, out);
}

// round 4
// speedup vs baseline: 2.9187x; 2.1347x over previous
#include <cuda_runtime.h>
#include <cuda_bf16.h>
#include <cstdint>

#define Bq 4
#define Sq 2048
#define Dq 1024
#define Hq 16
#define HDq 64
#define BSq (Bq*Sq)   // 8192
#define DD  (Dq*Dq)

// ---------------- scratch (__device__ globals; no allocs allowed) ----------
__device__ __nv_bfloat16 g_xh[BSq*Dq];
__device__ __nv_bfloat16 g_xl[BSq*Dq];
__device__ __nv_bfloat16 g_wh[4*DD];
__device__ __nv_bfloat16 g_wl[4*DD];
__device__ __nv_bfloat16 g_Qh[BSq*Dq];
__device__ __nv_bfloat16 g_Ql[BSq*Dq];
__device__ __nv_bfloat16 g_Kh[BSq*Dq];
__device__ __nv_bfloat16 g_Kl[BSq*Dq];
__device__ __nv_bfloat16 g_Vh[BSq*Dq];
__device__ __nv_bfloat16 g_Vl[BSq*Dq];
__device__ __nv_bfloat16 g_Ah[BSq*Dq];
__device__ __nv_bfloat16 g_Al[BSq*Dq];

__device__ __forceinline__ uint32_t smem_to_u32(const void* p) {
    uint32_t a;
    asm("{ .reg .u64 t; cvta.to.shared.u64 t, %1; cvt.u32.u64 %0, t; }"
        : "=r"(a) : "l"(p));
    return a;
}
__device__ __forceinline__ void cp16(uint32_t dst, const void* src) {
    asm volatile("cp.async.cg.shared.global [%0], [%1], 16;"
                 :: "r"(dst), "l"(src) : "memory");
}
__device__ __forceinline__ void cp_commit() {
    asm volatile("cp.async.commit_group;" ::: "memory");
}
template <int N>
__device__ __forceinline__ void cp_wait() {
    asm volatile("cp.async.wait_group %0;" :: "n"(N) : "memory");
}
__device__ __forceinline__ void ldsm_x4(uint32_t* r, uint32_t addr) {
    asm volatile("ldmatrix.sync.aligned.m8n8.x4.shared.b16 {%0,%1,%2,%3}, [%4];"
                 : "=r"(r[0]), "=r"(r[1]), "=r"(r[2]), "=r"(r[3]) : "r"(addr));
}
__device__ __forceinline__ void ldsm_x4_trans(uint32_t* r, uint32_t addr) {
    asm volatile("ldmatrix.sync.aligned.m8n8.x4.trans.shared.b16 {%0,%1,%2,%3}, [%4];"
                 : "=r"(r[0]), "=r"(r[1]), "=r"(r[2]), "=r"(r[3]) : "r"(addr));
}
__device__ __forceinline__ void mma_bf16(float* d, const uint32_t* a, const uint32_t* b) {
    asm volatile(
        "mma.sync.aligned.m16n8k16.row.col.f32.bf16.bf16.f32 "
        "{%0,%1,%2,%3}, {%4,%5,%6,%7}, {%8,%9}, {%0,%1,%2,%3};"
        : "+f"(d[0]), "+f"(d[1]), "+f"(d[2]), "+f"(d[3])
        : "r"(a[0]), "r"(a[1]), "r"(a[2]), "r"(a[3]), "r"(b[0]), "r"(b[1]));
}
__device__ __forceinline__ uint32_t pack_bf16(float x, float y) {
    __nv_bfloat162 v = __floats2bfloat162_rn(x, y);
    return *(uint32_t*)&v;
}

// ---------------------------------------------------------------------------
// fp32 -> (bf16 hi, bf16 lo) split
// ---------------------------------------------------------------------------
__global__ void split_kernel(const float4* __restrict__ x,
                             __nv_bfloat162* __restrict__ hi,
                             __nv_bfloat162* __restrict__ lo, int n4)
{
    int i = blockIdx.x * blockDim.x + threadIdx.x;
    if (i >= n4) return;
    float4 v = x[i];
    __nv_bfloat16 h0 = __float2bfloat16(v.x);
    __nv_bfloat16 h1 = __float2bfloat16(v.y);
    __nv_bfloat16 h2 = __float2bfloat16(v.z);
    __nv_bfloat16 h3 = __float2bfloat16(v.w);
    __nv_bfloat16 l0 = __float2bfloat16(v.x - __bfloat162float(h0));
    __nv_bfloat16 l1 = __float2bfloat16(v.y - __bfloat162float(h1));
    __nv_bfloat16 l2 = __float2bfloat16(v.z - __bfloat162float(h2));
    __nv_bfloat16 l3 = __float2bfloat16(v.w - __bfloat162float(h3));
    hi[i*2 + 0] = __nv_bfloat162(h0, h1);
    hi[i*2 + 1] = __nv_bfloat162(h2, h3);
    lo[i*2 + 0] = __nv_bfloat162(l0, l1);
    lo[i*2 + 1] = __nv_bfloat162(l2, l3);
}

// ---------------------------------------------------------------------------
// HMMA split-GEMM.  SPLIT=true: write bf16 hi/lo outputs; else fp32.
// CTA 128x128, 8 warps (warp tile 64x32), K-chunk 32, 2-stage cp.async.
// ---------------------------------------------------------------------------
#define GSTRIDE 40
#define GMAT    (128*GSTRIDE*2)
#define GSTAGE  (4*GMAT)
#define GSMEM   (2*GSTAGE)
#define NCHUNK  (Dq/32)

template<bool SPLIT>
__global__ __launch_bounds__(256, 2)
void gemm_mma_kernel(const __nv_bfloat16* __restrict__ Ah,
                     const __nv_bfloat16* __restrict__ Al,
                     const __nv_bfloat16* __restrict__ Wh,
                     const __nv_bfloat16* __restrict__ Wl,
                     const float* __restrict__ bias,
                     float* __restrict__ C,
                     __nv_bfloat16* __restrict__ Ch,
                     __nv_bfloat16* __restrict__ Cl)
{
    extern __shared__ char smem[];
    const uint32_t smem_base = smem_to_u32(smem);
    const int tid  = threadIdx.x;
    const int lane = tid & 31;
    const int wid  = tid >> 5;
    const int m0 = blockIdx.y * 128;
    const int n0 = blockIdx.x * 128;
    const int wm0 = (wid & 1) * 64;
    const int wn0 = (wid >> 1) * 32;

    const int id0 = tid, id1 = tid + 256;
    const int row0 = id0 >> 2, kq0 = (id0 & 3) * 8;
    const int row1 = id1 >> 2, kq1 = (id1 & 3) * 8;

    const __nv_bfloat16* gAh = Ah + (size_t)m0 * Dq;
    const __nv_bfloat16* gAl = Al + (size_t)m0 * Dq;
    const __nv_bfloat16* gWh = Wh + (size_t)n0 * Dq;
    const __nv_bfloat16* gWl = Wl + (size_t)n0 * Dq;

    float acc[4][4][4];
    #pragma unroll
    for (int i = 0; i < 4; i++)
        #pragma unroll
        for (int j = 0; j < 4; j++)
            #pragma unroll
            for (int r = 0; r < 4; r++) acc[i][j][r] = 0.f;

    auto issue = [&](int c, int s) {
        const int k0 = c * 32;
        uint32_t sb = smem_base + s * GSTAGE;
        uint32_t d0 = (uint32_t)(row0 * (GSTRIDE*2) + kq0 * 2);
        uint32_t d1 = (uint32_t)(row1 * (GSTRIDE*2) + kq1 * 2);
        size_t s0 = (size_t)row0 * Dq + k0 + kq0;
        size_t s1 = (size_t)row1 * Dq + k0 + kq1;
        cp16(sb + 0*GMAT + d0, gAh + s0);
        cp16(sb + 0*GMAT + d1, gAh + s1);
        cp16(sb + 1*GMAT + d0, gAl + s0);
        cp16(sb + 1*GMAT + d1, gAl + s1);
        cp16(sb + 2*GMAT + d0, gWh + s0);
        cp16(sb + 2*GMAT + d1, gWh + s1);
        cp16(sb + 3*GMAT + d0, gWl + s0);
        cp16(sb + 3*GMAT + d1, gWl + s1);
    };

    issue(0, 0);
    cp_commit();

    const int a_r = wm0 + (lane & 15);
    const int a_c = (lane >> 4) * 8;
    const int b_r = wn0 + (lane & 7) + ((lane >> 4) << 3);
    const int b_c = ((lane >> 3) & 1) * 8;

    for (int c = 0; c < NCHUNK; c++) {
        const int s = c & 1;
        if (c + 1 < NCHUNK) { issue(c + 1, s ^ 1); cp_commit(); }
        if (c + 1 < NCHUNK) cp_wait<1>(); else cp_wait<0>();
        __syncthreads();

        const uint32_t sb = smem_base + s * GSTAGE;
        const uint32_t aH = sb + 0*GMAT, aL = sb + 1*GMAT;
        const uint32_t wH = sb + 2*GMAT, wL = sb + 3*GMAT;

        #pragma unroll
        for (int kk = 0; kk < 2; kk++) {
            const int k16 = kk * 16;
            uint32_t bh[2][4], bl[2][4];
            #pragma unroll
            for (int jj = 0; jj < 2; jj++) {
                uint32_t off = (uint32_t)((b_r + jj*16) * (GSTRIDE*2) + (k16 + b_c) * 2);
                ldsm_x4(bh[jj], wH + off);
                ldsm_x4(bl[jj], wL + off);
            }
            #pragma unroll
            for (int i = 0; i < 4; i++) {
                uint32_t ah[4], al[4];
                uint32_t off = (uint32_t)((a_r + i*16) * (GSTRIDE*2) + (k16 + a_c) * 2);
                ldsm_x4(ah, aH + off);
                ldsm_x4(al, aL + off);
                #pragma unroll
                for (int j = 0; j < 4; j++) {
                    const uint32_t* bhp = &bh[j >> 1][(j & 1) * 2];
                    const uint32_t* blp = &bl[j >> 1][(j & 1) * 2];
                    mma_bf16(acc[i][j], ah, bhp);
                    mma_bf16(acc[i][j], ah, blp);
                    mma_bf16(acc[i][j], al, bhp);
                }
            }
        }
        __syncthreads();
    }

    // epilogue
    const int g = lane >> 2, t = lane & 3;
    #pragma unroll
    for (int j = 0; j < 4; j++) {
        const int col = n0 + wn0 + j*8 + t*2;
        const float bx = __ldg(&bias[col]);
        const float by = __ldg(&bias[col + 1]);
        #pragma unroll
        for (int i = 0; i < 4; i++) {
            const int r0 = m0 + wm0 + i*16 + g;
            float v0x = acc[i][j][0] + bx, v0y = acc[i][j][1] + by;
            float v1x = acc[i][j][2] + bx, v1y = acc[i][j][3] + by;
            if (SPLIT) {
                __nv_bfloat16 h0x = __float2bfloat16(v0x), h0y = __float2bfloat16(v0y);
                __nv_bfloat16 h1x = __float2bfloat16(v1x), h1y = __float2bfloat16(v1y);
                *(__nv_bfloat162*)&Ch[(size_t)r0 * Dq + col] = __nv_bfloat162(h0x, h0y);
                *(__nv_bfloat162*)&Ch[(size_t)(r0+8) * Dq + col] = __nv_bfloat162(h1x, h1y);
                *(__nv_bfloat162*)&Cl[(size_t)r0 * Dq + col] = __nv_bfloat162(
                    __float2bfloat16(v0x - __bfloat162float(h0x)),
                    __float2bfloat16(v0y - __bfloat162float(h0y)));
                *(__nv_bfloat162*)&Cl[(size_t)(r0+8) * Dq + col] = __nv_bfloat162(
                    __float2bfloat16(v1x - __bfloat162float(h1x)),
                    __float2bfloat16(v1y - __bfloat162float(h1y)));
            } else {
                float2 w0, w1;
                w0.x = v0x; w0.y = v0y; w1.x = v1x; w1.y = v1y;
                *(float2*)&C[(size_t)r0 * Dq + col] = w0;
                *(float2*)&C[(size_t)(r0 + 8) * Dq + col] = w1;
            }
        }
    }
}

// ---------------------------------------------------------------------------
// FA2-style HMMA attention, split-bf16 precision everywhere.
// CTA: 128 queries x one (b,h). 8 warps, warp tile m16 x n64. 32 key tiles of 64.
// ---------------------------------------------------------------------------
#define AST 72                      // padded bf16 row stride (144B = 9*16)
#define AT_TILE (64*AST*2)          // 9216 B per tile matrix
#define AT_SMEM (4*AT_TILE)         // 36864 B (Q staging aliases this)

__global__ __launch_bounds__(256)
void attn_mma_kernel(const __nv_bfloat16* __restrict__ Qh, const __nv_bfloat16* __restrict__ Ql,
                     const __nv_bfloat16* __restrict__ Kh, const __nv_bfloat16* __restrict__ Kl,
                     const __nv_bfloat16* __restrict__ Vh, const __nv_bfloat16* __restrict__ Vl,
                     __nv_bfloat16* __restrict__ Ah, __nv_bfloat16* __restrict__ Al)
{
    extern __shared__ char smem[];
    const uint32_t sbase = smem_to_u32(smem);
    const int tid = threadIdx.x, lane = tid & 31, wid = tid >> 5;
    const int bh = blockIdx.y, b = bh >> 4, h = bh & 15;
    const int q0 = blockIdx.x * 128;
    const int g = lane >> 2, t4 = lane & 3;

    // ---- stage Q (scaled by 1/8, exact in bf16) and pull fragments ----
    {
        __nv_bfloat16* sQh = (__nv_bfloat16*)smem;            // [128][AST]
        __nv_bfloat16* sQl = sQh + 128*AST;
        const int row = tid >> 1, halfo = (tid & 1) * 32;
        const __nv_bfloat162 sc = __floats2bfloat162_rn(0.125f, 0.125f);
        size_t gq = ((size_t)(b*Sq) + q0 + row) * Dq + h*HDq + halfo;
        #pragma unroll
        for (int u = 0; u < 4; u++) {
            uint4 xh4 = *(const uint4*)(Qh + gq + u*8);
            uint4 xl4 = *(const uint4*)(Ql + gq + u*8);
            __nv_bfloat162* ph = (__nv_bfloat162*)&xh4;
            __nv_bfloat162* pl = (__nv_bfloat162*)&xl4;
            #pragma unroll
            for (int e = 0; e < 4; e++) { ph[e] = __hmul2(ph[e], sc); pl[e] = __hmul2(pl[e], sc); }
            *(uint4*)&sQh[row*AST + halfo + u*8] = xh4;
            *(uint4*)&sQl[row*AST + halfo + u*8] = xl4;
        }
    }
    __syncthreads();
    uint32_t qh[4][4], ql[4][4];
    {
        uint32_t rowoff = (uint32_t)(((wid*16 + (lane & 15))*AST + (lane >> 4)*8) * 2);
        #pragma unroll
        for (int kk = 0; kk < 4; kk++) {
            ldsm_x4(qh[kk], sbase + rowoff + kk*32);
            ldsm_x4(ql[kk], sbase + (uint32_t)(128*AST*2) + rowoff + kk*32);
        }
    }
    __syncthreads();

    const uint32_t oKh = 0, oKl = AT_TILE, oVh = 2*AT_TILE, oVl = 3*AT_TILE;
    float m0 = -1e30f, m1 = -1e30f, l0 = 0.f, l1 = 0.f;
    float o[8][4];
    #pragma unroll
    for (int j = 0; j < 8; j++)
        #pragma unroll
        for (int r = 0; r < 4; r++) o[j][r] = 0.f;

    // B-fragment lane address components (K: normal; V: trans)
    const uint32_t kb_row = (lane & 7) + ((lane >> 4) & 1) * 8;
    const uint32_t kb_col = ((lane >> 3) & 1) * 8;
    const uint32_t vb_row = (lane & 7) + ((lane >> 3) & 1) * 8;
    const uint32_t vb_col = ((lane >> 4) & 1) * 8;

    for (int tile = 0; tile < Sq/64; tile++) {
        // ---- load K/V tile (hi+lo) ----
        {
            const int row = tid >> 2, d0 = (tid & 3) * 16;
            size_t gk = ((size_t)(b*Sq) + tile*64 + row) * Dq + h*HDq + d0;
            uint32_t so = (uint32_t)((row*AST + d0) * 2);
            uint4 a0 = *(const uint4*)(Kh + gk); uint4 a1 = *(const uint4*)(Kh + gk + 8);
            uint4 b0 = *(const uint4*)(Kl + gk); uint4 b1 = *(const uint4*)(Kl + gk + 8);
            uint4 c0 = *(const uint4*)(Vh + gk); uint4 c1 = *(const uint4*)(Vh + gk + 8);
            uint4 e0 = *(const uint4*)(Vl + gk); uint4 e1 = *(const uint4*)(Vl + gk + 8);
            *(uint4*)(smem + oKh + so) = a0; *(uint4*)(smem + oKh + so + 16) = a1;
            *(uint4*)(smem + oKl + so) = b0; *(uint4*)(smem + oKl + so + 16) = b1;
            *(uint4*)(smem + oVh + so) = c0; *(uint4*)(smem + oVh + so + 16) = c1;
            *(uint4*)(smem + oVl + so) = e0; *(uint4*)(smem + oVl + so + 16) = e1;
        }
        __syncthreads();

        // ---- S = (Q/8) K^T, 3 split terms ----
        float s[8][4];
        #pragma unroll
        for (int j = 0; j < 8; j++)
            #pragma unroll
            for (int r = 0; r < 4; r++) s[j][r] = 0.f;
        #pragma unroll
        for (int kk = 0; kk < 4; kk++) {
            #pragma unroll
            for (int jj = 0; jj < 4; jj++) {
                uint32_t off = (uint32_t)(((jj*16 + kb_row)*AST + kk*16 + kb_col) * 2);
                uint32_t kf[4], lf[4];
                ldsm_x4(kf, sbase + oKh + off);
                ldsm_x4(lf, sbase + oKl + off);
                mma_bf16(s[2*jj],   qh[kk], &kf[0]);
                mma_bf16(s[2*jj+1], qh[kk], &kf[2]);
                mma_bf16(s[2*jj],   qh[kk], &lf[0]);
                mma_bf16(s[2*jj+1], qh[kk], &lf[2]);
                mma_bf16(s[2*jj],   ql[kk], &kf[0]);
                mma_bf16(s[2*jj+1], ql[kk], &kf[2]);
            }
        }

        // ---- online softmax (rows g and g+8; quad shfl over t4) ----
        float mx0 = -1e30f, mx1 = -1e30f;
        #pragma unroll
        for (int j = 0; j < 8; j++) {
            mx0 = fmaxf(mx0, fmaxf(s[j][0], s[j][1]));
            mx1 = fmaxf(mx1, fmaxf(s[j][2], s[j][3]));
        }
        mx0 = fmaxf(mx0, __shfl_xor_sync(0xffffffffu, mx0, 1));
        mx0 = fmaxf(mx0, __shfl_xor_sync(0xffffffffu, mx0, 2));
        mx1 = fmaxf(mx1, __shfl_xor_sync(0xffffffffu, mx1, 1));
        mx1 = fmaxf(mx1, __shfl_xor_sync(0xffffffffu, mx1, 2));
        float mn0 = fmaxf(m0, mx0), mn1 = fmaxf(m1, mx1);
        float c0 = __expf(m0 - mn0), c1 = __expf(m1 - mn1);
        float sum0 = 0.f, sum1 = 0.f;
        #pragma unroll
        for (int j = 0; j < 8; j++) {
            s[j][0] = __expf(s[j][0] - mn0); sum0 += s[j][0];
            s[j][1] = __expf(s[j][1] - mn0); sum0 += s[j][1];
            s[j][2] = __expf(s[j][2] - mn1); sum1 += s[j][2];
            s[j][3] = __expf(s[j][3] - mn1); sum1 += s[j][3];
        }
        sum0 += __shfl_xor_sync(0xffffffffu, sum0, 1);
        sum0 += __shfl_xor_sync(0xffffffffu, sum0, 2);
        sum1 += __shfl_xor_sync(0xffffffffu, sum1, 1);
        sum1 += __shfl_xor_sync(0xffffffffu, sum1, 2);
        m0 = mn0; m1 = mn1;
        l0 = l0 * c0 + sum0;
        l1 = l1 * c1 + sum1;
        #pragma unroll
        for (int j = 0; j < 8; j++) {
            o[j][0] *= c0; o[j][1] *= c0;
            o[j][2] *= c1; o[j][3] *= c1;
        }

        // ---- O += P V, 3 split terms; P frag built from S regs ----
        #pragma unroll
        for (int kk = 0; kk < 4; kk++) {
            uint32_t pah[4], pal[4];
            {
                float* s0 = s[2*kk];
                float* s1 = s[2*kk+1];
                pah[0] = pack_bf16(s0[0], s0[1]);
                pah[1] = pack_bf16(s0[2], s0[3]);
                pah[2] = pack_bf16(s1[0], s1[1]);
                pah[3] = pack_bf16(s1[2], s1[3]);
                __nv_bfloat162 h;
                h = *(__nv_bfloat162*)&pah[0];
                pal[0] = pack_bf16(s0[0] - __bfloat162float(h.x), s0[1] - __bfloat162float(h.y));
                h = *(__nv_bfloat162*)&pah[1];
                pal[1] = pack_bf16(s0[2] - __bfloat162float(h.x), s0[3] - __bfloat162float(h.y));
                h = *(__nv_bfloat162*)&pah[2];
                pal[2] = pack_bf16(s1[0] - __bfloat162float(h.x), s1[1] - __bfloat162float(h.y));
                h = *(__nv_bfloat162*)&pah[3];
                pal[3] = pack_bf16(s1[2] - __bfloat162float(h.x), s1[3] - __bfloat162float(h.y));
            }
            #pragma unroll
            for (int jj = 0; jj < 4; jj++) {
                uint32_t off = (uint32_t)(((kk*16 + vb_row)*AST + jj*16 + vb_col) * 2);
                uint32_t vh[4], vl[4];
                ldsm_x4_trans(vh, sbase + oVh + off);
                ldsm_x4_trans(vl, sbase + oVl + off);
                mma_bf16(o[2*jj],   pah, &vh[0]);
                mma_bf16(o[2*jj+1], pah, &vh[2]);
                mma_bf16(o[2*jj],   pah, &vl[0]);
                mma_bf16(o[2*jj+1], pah, &vl[2]);
                mma_bf16(o[2*jj],   pal, &vh[0]);
                mma_bf16(o[2*jj+1], pal, &vh[2]);
            }
        }
        __syncthreads();
    }

    // ---- epilogue: normalize, split to bf16 hi/lo ----
    float inv0 = 1.0f / l0, inv1 = 1.0f / l1;
    const int row0 = q0 + wid*16 + g;
    size_t ob0 = ((size_t)(b*Sq) + row0) * Dq + h*HDq;
    size_t ob1 = ob0 + (size_t)8 * Dq;
    #pragma unroll
    for (int j = 0; j < 8; j++) {
        const int c = j*8 + t4*2;
        float f0 = o[j][0] * inv0, f1 = o[j][1] * inv0;
        float f2 = o[j][2] * inv1, f3 = o[j][3] * inv1;
        __nv_bfloat16 h0 = __float2bfloat16(f0), h1 = __float2bfloat16(f1);
        __nv_bfloat16 h2 = __float2bfloat16(f2), h3 = __float2bfloat16(f3);
        *(__nv_bfloat162*)&Ah[ob0 + c] = __nv_bfloat162(h0, h1);
        *(__nv_bfloat162*)&Ah[ob1 + c] = __nv_bfloat162(h2, h3);
        *(__nv_bfloat162*)&Al[ob0 + c] = __nv_bfloat162(
            __float2bfloat16(f0 - __bfloat162float(h0)),
            __float2bfloat16(f1 - __bfloat162float(h1)));
        *(__nv_bfloat162*)&Al[ob1 + c] = __nv_bfloat162(
            __float2bfloat16(f2 - __bfloat162float(h2)),
            __float2bfloat16(f3 - __bfloat162float(h3)));
    }
}

// ---------------------------------------------------------------------------
extern "C" void kernel_launch(void* const* d_in, const int* in_sizes, int n_in,
                              void* d_out, int out_size)
{
    const float* q   = (const float*)d_in[0];
    const float* k   = (const float*)d_in[1];
    const float* v   = (const float*)d_in[2];
    const float* w_q = (const float*)d_in[3];
    const float* b_q = (const float*)d_in[4];
    const float* w_k = (const float*)d_in[5];
    const float* b_k = (const float*)d_in[6];
    const float* w_v = (const float*)d_in[7];
    const float* b_v = (const float*)d_in[8];
    const float* w_fc= (const float*)d_in[9];
    const float* b_fc= (const float*)d_in[10];
    float* out = (float*)d_out;

    __nv_bfloat16 *xh, *xl, *wh, *wl, *Qh, *Ql, *Kh, *Kl, *Vh, *Vl, *Ahp, *Alp;
    cudaGetSymbolAddress((void**)&xh, g_xh);
    cudaGetSymbolAddress((void**)&xl, g_xl);
    cudaGetSymbolAddress((void**)&wh, g_wh);
    cudaGetSymbolAddress((void**)&wl, g_wl);
    cudaGetSymbolAddress((void**)&Qh, g_Qh);
    cudaGetSymbolAddress((void**)&Ql, g_Ql);
    cudaGetSymbolAddress((void**)&Kh, g_Kh);
    cudaGetSymbolAddress((void**)&Kl, g_Kl);
    cudaGetSymbolAddress((void**)&Vh, g_Vh);
    cudaGetSymbolAddress((void**)&Vl, g_Vl);
    cudaGetSymbolAddress((void**)&Ahp, g_Ah);
    cudaGetSymbolAddress((void**)&Alp, g_Al);

    cudaFuncSetAttribute(gemm_mma_kernel<true>,
                         cudaFuncAttributeMaxDynamicSharedMemorySize, GSMEM);
    cudaFuncSetAttribute(gemm_mma_kernel<false>,
                         cudaFuncAttributeMaxDynamicSharedMemorySize, GSMEM);
    cudaFuncSetAttribute(attn_mma_kernel,
                         cudaFuncAttributeMaxDynamicSharedMemorySize, AT_SMEM);

    const int actN4 = BSq*Dq/4;
    const int wN4   = DD/4;
    dim3 sblk(256);
    dim3 sgrid_act((actN4 + 255)/256);
    dim3 sgrid_w((wN4 + 255)/256);
    dim3 tcgrid(Dq/128, BSq/128);

    // weight splits
    split_kernel<<<sgrid_w, sblk>>>((const float4*)w_q,  (__nv_bfloat162*)(wh + 0*DD), (__nv_bfloat162*)(wl + 0*DD), wN4);
    split_kernel<<<sgrid_w, sblk>>>((const float4*)w_k,  (__nv_bfloat162*)(wh + 1*DD), (__nv_bfloat162*)(wl + 1*DD), wN4);
    split_kernel<<<sgrid_w, sblk>>>((const float4*)w_v,  (__nv_bfloat162*)(wh + 2*DD), (__nv_bfloat162*)(wl + 2*DD), wN4);
    split_kernel<<<sgrid_w, sblk>>>((const float4*)w_fc, (__nv_bfloat162*)(wh + 3*DD), (__nv_bfloat162*)(wl + 3*DD), wN4);

    // projections -> bf16 hi/lo outputs
    split_kernel<<<sgrid_act, sblk>>>((const float4*)q, (__nv_bfloat162*)xh, (__nv_bfloat162*)xl, actN4);
    gemm_mma_kernel<true><<<tcgrid, 256, GSMEM>>>(xh, xl, wh + 0*DD, wl + 0*DD, b_q, nullptr, Qh, Ql);
    split_kernel<<<sgrid_act, sblk>>>((const float4*)k, (__nv_bfloat162*)xh, (__nv_bfloat162*)xl, actN4);
    gemm_mma_kernel<true><<<tcgrid, 256, GSMEM>>>(xh, xl, wh + 1*DD, wl + 1*DD, b_k, nullptr, Kh, Kl);
    split_kernel<<<sgrid_act, sblk>>>((const float4*)v, (__nv_bfloat162*)xh, (__nv_bfloat162*)xl, actN4);
    gemm_mma_kernel<true><<<tcgrid, 256, GSMEM>>>(xh, xl, wh + 2*DD, wl + 2*DD, b_v, nullptr, Vh, Vl);

    // attention (tensor cores, split precision), writes split output
    attn_mma_kernel<<<dim3(Sq/128, Bq*Hq), 256, AT_SMEM>>>(Qh, Ql, Kh, Kl, Vh, Vl, Ahp, Alp);

    // output projection (fp32 out)
    gemm_mma_kernel<false><<<tcgrid, 256, GSMEM>>>(Ahp, Alp, wh + 3*DD, wl + 3*DD, b_fc, out, nullptr, nullptr);
}

// round 5
// speedup vs baseline: 3.1796x; 1.0894x over previous
#include <cuda_runtime.h>
#include <cuda_bf16.h>
#include <cstdint>

#define Bq 4
#define Sq 2048
#define Dq 1024
#define Hq 16
#define HDq 64
#define BSq (Bq*Sq)   // 8192
#define DD  (Dq*Dq)

// ---------------- scratch (__device__ globals; no allocs allowed) ----------
__device__ __nv_bfloat16 g_xh[BSq*Dq];
__device__ __nv_bfloat16 g_xl[BSq*Dq];
__device__ __nv_bfloat16 g_wh[4*DD];
__device__ __nv_bfloat16 g_wl[4*DD];
__device__ __nv_bfloat16 g_Qh[BSq*Dq];
__device__ __nv_bfloat16 g_Ql[BSq*Dq];
__device__ __nv_bfloat16 g_Kh[BSq*Dq];
__device__ __nv_bfloat16 g_Kl[BSq*Dq];
__device__ __nv_bfloat16 g_Vh[BSq*Dq];
__device__ __nv_bfloat16 g_Vl[BSq*Dq];
__device__ __nv_bfloat16 g_Ah[BSq*Dq];
__device__ __nv_bfloat16 g_Al[BSq*Dq];

__device__ __forceinline__ uint32_t smem_to_u32(const void* p) {
    uint32_t a;
    asm("{ .reg .u64 t; cvta.to.shared.u64 t, %1; cvt.u32.u64 %0, t; }"
        : "=r"(a) : "l"(p));
    return a;
}
__device__ __forceinline__ void cp16(uint32_t dst, const void* src) {
    asm volatile("cp.async.cg.shared.global [%0], [%1], 16;"
                 :: "r"(dst), "l"(src) : "memory");
}
__device__ __forceinline__ void cp_commit() {
    asm volatile("cp.async.commit_group;" ::: "memory");
}
template <int N>
__device__ __forceinline__ void cp_wait() {
    asm volatile("cp.async.wait_group %0;" :: "n"(N) : "memory");
}
__device__ __forceinline__ void ldsm_x4(uint32_t* r, uint32_t addr) {
    asm volatile("ldmatrix.sync.aligned.m8n8.x4.shared.b16 {%0,%1,%2,%3}, [%4];"
                 : "=r"(r[0]), "=r"(r[1]), "=r"(r[2]), "=r"(r[3]) : "r"(addr));
}
__device__ __forceinline__ void ldsm_x4_trans(uint32_t* r, uint32_t addr) {
    asm volatile("ldmatrix.sync.aligned.m8n8.x4.trans.shared.b16 {%0,%1,%2,%3}, [%4];"
                 : "=r"(r[0]), "=r"(r[1]), "=r"(r[2]), "=r"(r[3]) : "r"(addr));
}
__device__ __forceinline__ void mma_bf16(float* d, const uint32_t* a, const uint32_t* b) {
    asm volatile(
        "mma.sync.aligned.m16n8k16.row.col.f32.bf16.bf16.f32 "
        "{%0,%1,%2,%3}, {%4,%5,%6,%7}, {%8,%9}, {%0,%1,%2,%3};"
        : "+f"(d[0]), "+f"(d[1]), "+f"(d[2]), "+f"(d[3])
        : "r"(a[0]), "r"(a[1]), "r"(a[2]), "r"(a[3]), "r"(b[0]), "r"(b[1]));
}
__device__ __forceinline__ uint32_t pack_bf16(float x, float y) {
    __nv_bfloat162 v = __floats2bfloat162_rn(x, y);
    return *(uint32_t*)&v;
}

// ---------------------------------------------------------------------------
// fp32 -> (bf16 hi, bf16 lo) split
// ---------------------------------------------------------------------------
__global__ void split_kernel(const float4* __restrict__ x,
                             __nv_bfloat162* __restrict__ hi,
                             __nv_bfloat162* __restrict__ lo, int n4)
{
    int i = blockIdx.x * blockDim.x + threadIdx.x;
    if (i >= n4) return;
    float4 v = x[i];
    __nv_bfloat16 h0 = __float2bfloat16(v.x);
    __nv_bfloat16 h1 = __float2bfloat16(v.y);
    __nv_bfloat16 h2 = __float2bfloat16(v.z);
    __nv_bfloat16 h3 = __float2bfloat16(v.w);
    __nv_bfloat16 l0 = __float2bfloat16(v.x - __bfloat162float(h0));
    __nv_bfloat16 l1 = __float2bfloat16(v.y - __bfloat162float(h1));
    __nv_bfloat16 l2 = __float2bfloat16(v.z - __bfloat162float(h2));
    __nv_bfloat16 l3 = __float2bfloat16(v.w - __bfloat162float(h3));
    hi[i*2 + 0] = __nv_bfloat162(h0, h1);
    hi[i*2 + 1] = __nv_bfloat162(h2, h3);
    lo[i*2 + 0] = __nv_bfloat162(l0, l1);
    lo[i*2 + 1] = __nv_bfloat162(l2, l3);
}

// ---------------------------------------------------------------------------
// HMMA split-GEMM.  SPLIT=true: write bf16 hi/lo outputs; else fp32.
// CTA 128x128, 8 warps (warp tile 64x32), K-chunk 32, 2-stage cp.async.
// ---------------------------------------------------------------------------
#define GSTRIDE 40
#define GMAT    (128*GSTRIDE*2)
#define GSTAGE  (4*GMAT)
#define GSMEM   (2*GSTAGE)
#define NCHUNK  (Dq/32)

template<bool SPLIT>
__global__ __launch_bounds__(256, 2)
void gemm_mma_kernel(const __nv_bfloat16* __restrict__ Ah,
                     const __nv_bfloat16* __restrict__ Al,
                     const __nv_bfloat16* __restrict__ Wh,
                     const __nv_bfloat16* __restrict__ Wl,
                     const float* __restrict__ bias,
                     float* __restrict__ C,
                     __nv_bfloat16* __restrict__ Ch,
                     __nv_bfloat16* __restrict__ Cl)
{
    extern __shared__ char smem[];
    const uint32_t smem_base = smem_to_u32(smem);
    const int tid  = threadIdx.x;
    const int lane = tid & 31;
    const int wid  = tid >> 5;
    const int m0 = blockIdx.y * 128;
    const int n0 = blockIdx.x * 128;
    const int wm0 = (wid & 1) * 64;
    const int wn0 = (wid >> 1) * 32;

    const int id0 = tid, id1 = tid + 256;
    const int row0 = id0 >> 2, kq0 = (id0 & 3) * 8;
    const int row1 = id1 >> 2, kq1 = (id1 & 3) * 8;

    const __nv_bfloat16* gAh = Ah + (size_t)m0 * Dq;
    const __nv_bfloat16* gAl = Al + (size_t)m0 * Dq;
    const __nv_bfloat16* gWh = Wh + (size_t)n0 * Dq;
    const __nv_bfloat16* gWl = Wl + (size_t)n0 * Dq;

    float acc[4][4][4];
    #pragma unroll
    for (int i = 0; i < 4; i++)
        #pragma unroll
        for (int j = 0; j < 4; j++)
            #pragma unroll
            for (int r = 0; r < 4; r++) acc[i][j][r] = 0.f;

    auto issue = [&](int c, int s) {
        const int k0 = c * 32;
        uint32_t sb = smem_base + s * GSTAGE;
        uint32_t d0 = (uint32_t)(row0 * (GSTRIDE*2) + kq0 * 2);
        uint32_t d1 = (uint32_t)(row1 * (GSTRIDE*2) + kq1 * 2);
        size_t s0 = (size_t)row0 * Dq + k0 + kq0;
        size_t s1 = (size_t)row1 * Dq + k0 + kq1;
        cp16(sb + 0*GMAT + d0, gAh + s0);
        cp16(sb + 0*GMAT + d1, gAh + s1);
        cp16(sb + 1*GMAT + d0, gAl + s0);
        cp16(sb + 1*GMAT + d1, gAl + s1);
        cp16(sb + 2*GMAT + d0, gWh + s0);
        cp16(sb + 2*GMAT + d1, gWh + s1);
        cp16(sb + 3*GMAT + d0, gWl + s0);
        cp16(sb + 3*GMAT + d1, gWl + s1);
    };

    issue(0, 0);
    cp_commit();

    const int a_r = wm0 + (lane & 15);
    const int a_c = (lane >> 4) * 8;
    const int b_r = wn0 + (lane & 7) + ((lane >> 4) << 3);
    const int b_c = ((lane >> 3) & 1) * 8;

    for (int c = 0; c < NCHUNK; c++) {
        const int s = c & 1;
        if (c + 1 < NCHUNK) { issue(c + 1, s ^ 1); cp_commit(); }
        if (c + 1 < NCHUNK) cp_wait<1>(); else cp_wait<0>();
        __syncthreads();

        const uint32_t sb = smem_base + s * GSTAGE;
        const uint32_t aH = sb + 0*GMAT, aL = sb + 1*GMAT;
        const uint32_t wH = sb + 2*GMAT, wL = sb + 3*GMAT;

        #pragma unroll
        for (int kk = 0; kk < 2; kk++) {
            const int k16 = kk * 16;
            uint32_t bh[2][4], bl[2][4];
            #pragma unroll
            for (int jj = 0; jj < 2; jj++) {
                uint32_t off = (uint32_t)((b_r + jj*16) * (GSTRIDE*2) + (k16 + b_c) * 2);
                ldsm_x4(bh[jj], wH + off);
                ldsm_x4(bl[jj], wL + off);
            }
            #pragma unroll
            for (int i = 0; i < 4; i++) {
                uint32_t ah[4], al[4];
                uint32_t off = (uint32_t)((a_r + i*16) * (GSTRIDE*2) + (k16 + a_c) * 2);
                ldsm_x4(ah, aH + off);
                ldsm_x4(al, aL + off);
                #pragma unroll
                for (int j = 0; j < 4; j++) {
                    const uint32_t* bhp = &bh[j >> 1][(j & 1) * 2];
                    const uint32_t* blp = &bl[j >> 1][(j & 1) * 2];
                    mma_bf16(acc[i][j], ah, bhp);
                    mma_bf16(acc[i][j], ah, blp);
                    mma_bf16(acc[i][j], al, bhp);
                }
            }
        }
        __syncthreads();
    }

    // epilogue
    const int g = lane >> 2, t = lane & 3;
    #pragma unroll
    for (int j = 0; j < 4; j++) {
        const int col = n0 + wn0 + j*8 + t*2;
        const float bx = __ldg(&bias[col]);
        const float by = __ldg(&bias[col + 1]);
        #pragma unroll
        for (int i = 0; i < 4; i++) {
            const int r0 = m0 + wm0 + i*16 + g;
            float v0x = acc[i][j][0] + bx, v0y = acc[i][j][1] + by;
            float v1x = acc[i][j][2] + bx, v1y = acc[i][j][3] + by;
            if (SPLIT) {
                __nv_bfloat16 h0x = __float2bfloat16(v0x), h0y = __float2bfloat16(v0y);
                __nv_bfloat16 h1x = __float2bfloat16(v1x), h1y = __float2bfloat16(v1y);
                *(__nv_bfloat162*)&Ch[(size_t)r0 * Dq + col] = __nv_bfloat162(h0x, h0y);
                *(__nv_bfloat162*)&Ch[(size_t)(r0+8) * Dq + col] = __nv_bfloat162(h1x, h1y);
                *(__nv_bfloat162*)&Cl[(size_t)r0 * Dq + col] = __nv_bfloat162(
                    __float2bfloat16(v0x - __bfloat162float(h0x)),
                    __float2bfloat16(v0y - __bfloat162float(h0y)));
                *(__nv_bfloat162*)&Cl[(size_t)(r0+8) * Dq + col] = __nv_bfloat162(
                    __float2bfloat16(v1x - __bfloat162float(h1x)),
                    __float2bfloat16(v1y - __bfloat162float(h1y)));
            } else {
                float2 w0, w1;
                w0.x = v0x; w0.y = v0y; w1.x = v1x; w1.y = v1y;
                *(float2*)&C[(size_t)r0 * Dq + col] = w0;
                *(float2*)&C[(size_t)(r0 + 8) * Dq + col] = w1;
            }
        }
    }
}

// ---------------------------------------------------------------------------
// FA2-style HMMA attention with 2-stage cp.async K/V pipeline.
// CTA: 128 queries x one (b,h). 8 warps, warp tile m16 x n64. 32 key tiles of 64.
// smem: 2 stages x {Kh,Kl,Vh,Vl} 64x64 bf16 tiles (AST-padded).
// ---------------------------------------------------------------------------
#define AST 72                       // padded bf16 row stride (144 B, 16B-aligned)
#define AT_TILE  (64*AST*2)          // 9216 B per matrix
#define AT_STAGE (4*AT_TILE)         // 36864 B per stage
#define AT_SMEM  (2*AT_STAGE)        // 73728 B

__global__ __launch_bounds__(256, 2)
void attn_mma_kernel(const __nv_bfloat16* __restrict__ Qh, const __nv_bfloat16* __restrict__ Ql,
                     const __nv_bfloat16* __restrict__ Kh, const __nv_bfloat16* __restrict__ Kl,
                     const __nv_bfloat16* __restrict__ Vh, const __nv_bfloat16* __restrict__ Vl,
                     __nv_bfloat16* __restrict__ Ah, __nv_bfloat16* __restrict__ Al)
{
    extern __shared__ char smem[];
    const uint32_t sbase = smem_to_u32(smem);
    const int tid = threadIdx.x, lane = tid & 31, wid = tid >> 5;
    const int bh = blockIdx.y, b = bh >> 4, h = bh & 15;
    const int q0 = blockIdx.x * 128;
    const int g = lane >> 2, t4 = lane & 3;

    // ---- stage Q (scaled by 1/8, exact in bf16) into stage-0 region ----
    {
        __nv_bfloat16* sQh = (__nv_bfloat16*)smem;            // 128 x AST
        __nv_bfloat16* sQl = sQh + 128*AST;                   // +18432 B
        const int row = tid >> 1, halfo = (tid & 1) * 32;
        const __nv_bfloat162 sc = __floats2bfloat162_rn(0.125f, 0.125f);
        size_t gq = ((size_t)(b*Sq) + q0 + row) * Dq + h*HDq + halfo;
        #pragma unroll
        for (int u = 0; u < 4; u++) {
            uint4 xh4 = *(const uint4*)(Qh + gq + u*8);
            uint4 xl4 = *(const uint4*)(Ql + gq + u*8);
            __nv_bfloat162* ph = (__nv_bfloat162*)&xh4;
            __nv_bfloat162* pl = (__nv_bfloat162*)&xl4;
            #pragma unroll
            for (int e = 0; e < 4; e++) { ph[e] = __hmul2(ph[e], sc); pl[e] = __hmul2(pl[e], sc); }
            *(uint4*)&sQh[row*AST + halfo + u*8] = xh4;
            *(uint4*)&sQl[row*AST + halfo + u*8] = xl4;
        }
    }
    __syncthreads();
    uint32_t qh[4][4], ql[4][4];
    {
        uint32_t rowoff = (uint32_t)(((wid*16 + (lane & 15))*AST + (lane >> 4)*8) * 2);
        #pragma unroll
        for (int kk = 0; kk < 4; kk++) {
            ldsm_x4(qh[kk], sbase + rowoff + kk*32);
            ldsm_x4(ql[kk], sbase + (uint32_t)(128*AST*2) + rowoff + kk*32);
        }
    }
    __syncthreads();   // Q frags in regs; smem free for KV stages

    // KV cp.async issue: each thread 8 x cp16 (2 per matrix)
    const int krow = tid >> 2, kd0 = (tid & 3) * 16;
    const size_t kvrowbase = (size_t)(b*Sq) * Dq + h*HDq + (size_t)krow * Dq + kd0;
    const uint32_t so = (uint32_t)((krow*AST + kd0) * 2);

    auto issue_kv = [&](int tile, int s) {
        size_t gk = kvrowbase + (size_t)tile * 64 * Dq;
        uint32_t sb = sbase + s * AT_STAGE;
        cp16(sb + 0*AT_TILE + so,      Kh + gk);
        cp16(sb + 0*AT_TILE + so + 16, Kh + gk + 8);
        cp16(sb + 1*AT_TILE + so,      Kl + gk);
        cp16(sb + 1*AT_TILE + so + 16, Kl + gk + 8);
        cp16(sb + 2*AT_TILE + so,      Vh + gk);
        cp16(sb + 2*AT_TILE + so + 16, Vh + gk + 8);
        cp16(sb + 3*AT_TILE + so,      Vl + gk);
        cp16(sb + 3*AT_TILE + so + 16, Vl + gk + 8);
    };

    issue_kv(0, 0); cp_commit();
    issue_kv(1, 1); cp_commit();

    float m0 = -1e30f, m1 = -1e30f, l0 = 0.f, l1 = 0.f;
    float o[8][4];
    #pragma unroll
    for (int j = 0; j < 8; j++)
        #pragma unroll
        for (int r = 0; r < 4; r++) o[j][r] = 0.f;

    const uint32_t kb_row = (lane & 7) + ((lane >> 4) & 1) * 8;
    const uint32_t kb_col = ((lane >> 3) & 1) * 8;
    const uint32_t vb_row = (lane & 7) + ((lane >> 3) & 1) * 8;
    const uint32_t vb_col = ((lane >> 4) & 1) * 8;

    for (int tile = 0; tile < Sq/64; tile++) {
        const int s = tile & 1;
        const uint32_t sb = sbase + s * AT_STAGE;
        const uint32_t oKh = sb, oKl = sb + AT_TILE, oVh = sb + 2*AT_TILE, oVl = sb + 3*AT_TILE;

        cp_wait<1>();
        __syncthreads();   // stage s ready for all warps

        // ---- S = (Q/8) K^T, 3 split terms ----
        float sAcc[8][4];
        #pragma unroll
        for (int j = 0; j < 8; j++)
            #pragma unroll
            for (int r = 0; r < 4; r++) sAcc[j][r] = 0.f;
        #pragma unroll
        for (int kk = 0; kk < 4; kk++) {
            #pragma unroll
            for (int jj = 0; jj < 4; jj++) {
                uint32_t off = (uint32_t)(((jj*16 + kb_row)*AST + kk*16 + kb_col) * 2);
                uint32_t kf[4], lf[4];
                ldsm_x4(kf, oKh + off);
                ldsm_x4(lf, oKl + off);
                mma_bf16(sAcc[2*jj],   qh[kk], &kf[0]);
                mma_bf16(sAcc[2*jj+1], qh[kk], &kf[2]);
                mma_bf16(sAcc[2*jj],   qh[kk], &lf[0]);
                mma_bf16(sAcc[2*jj+1], qh[kk], &lf[2]);
                mma_bf16(sAcc[2*jj],   ql[kk], &kf[0]);
                mma_bf16(sAcc[2*jj+1], ql[kk], &kf[2]);
            }
        }

        // ---- online softmax (rows g and g+8; quad shfl over t4) ----
        float mx0 = -1e30f, mx1 = -1e30f;
        #pragma unroll
        for (int j = 0; j < 8; j++) {
            mx0 = fmaxf(mx0, fmaxf(sAcc[j][0], sAcc[j][1]));
            mx1 = fmaxf(mx1, fmaxf(sAcc[j][2], sAcc[j][3]));
        }
        mx0 = fmaxf(mx0, __shfl_xor_sync(0xffffffffu, mx0, 1));
        mx0 = fmaxf(mx0, __shfl_xor_sync(0xffffffffu, mx0, 2));
        mx1 = fmaxf(mx1, __shfl_xor_sync(0xffffffffu, mx1, 1));
        mx1 = fmaxf(mx1, __shfl_xor_sync(0xffffffffu, mx1, 2));
        float mn0 = fmaxf(m0, mx0), mn1 = fmaxf(m1, mx1);
        float c0 = __expf(m0 - mn0), c1 = __expf(m1 - mn1);
        float sum0 = 0.f, sum1 = 0.f;
        #pragma unroll
        for (int j = 0; j < 8; j++) {
            sAcc[j][0] = __expf(sAcc[j][0] - mn0); sum0 += sAcc[j][0];
            sAcc[j][1] = __expf(sAcc[j][1] - mn0); sum0 += sAcc[j][1];
            sAcc[j][2] = __expf(sAcc[j][2] - mn1); sum1 += sAcc[j][2];
            sAcc[j][3] = __expf(sAcc[j][3] - mn1); sum1 += sAcc[j][3];
        }
        sum0 += __shfl_xor_sync(0xffffffffu, sum0, 1);
        sum0 += __shfl_xor_sync(0xffffffffu, sum0, 2);
        sum1 += __shfl_xor_sync(0xffffffffu, sum1, 1);
        sum1 += __shfl_xor_sync(0xffffffffu, sum1, 2);
        m0 = mn0; m1 = mn1;
        l0 = l0 * c0 + sum0;
        l1 = l1 * c1 + sum1;
        #pragma unroll
        for (int j = 0; j < 8; j++) {
            o[j][0] *= c0; o[j][1] *= c0;
            o[j][2] *= c1; o[j][3] *= c1;
        }

        // ---- O += P V, 3 split terms; P frags built in place from sAcc ----
        #pragma unroll
        for (int kk = 0; kk < 4; kk++) {
            uint32_t pah[4], pal[4];
            {
                float* s0 = sAcc[2*kk];
                float* s1 = sAcc[2*kk+1];
                pah[0] = pack_bf16(s0[0], s0[1]);
                pah[1] = pack_bf16(s0[2], s0[3]);
                pah[2] = pack_bf16(s1[0], s1[1]);
                pah[3] = pack_bf16(s1[2], s1[3]);
                __nv_bfloat162 hh;
                hh = *(__nv_bfloat162*)&pah[0];
                pal[0] = pack_bf16(s0[0] - __bfloat162float(hh.x), s0[1] - __bfloat162float(hh.y));
                hh = *(__nv_bfloat162*)&pah[1];
                pal[1] = pack_bf16(s0[2] - __bfloat162float(hh.x), s0[3] - __bfloat162float(hh.y));
                hh = *(__nv_bfloat162*)&pah[2];
                pal[2] = pack_bf16(s1[0] - __bfloat162float(hh.x), s1[1] - __bfloat162float(hh.y));
                hh = *(__nv_bfloat162*)&pah[3];
                pal[3] = pack_bf16(s1[2] - __bfloat162float(hh.x), s1[3] - __bfloat162float(hh.y));
            }
            #pragma unroll
            for (int jj = 0; jj < 4; jj++) {
                uint32_t off = (uint32_t)(((kk*16 + vb_row)*AST + jj*16 + vb_col) * 2);
                uint32_t vh[4], vl[4];
                ldsm_x4_trans(vh, oVh + off);
                ldsm_x4_trans(vl, oVl + off);
                mma_bf16(o[2*jj],   pah, &vh[0]);
                mma_bf16(o[2*jj+1], pah, &vh[2]);
                mma_bf16(o[2*jj],   pah, &vl[0]);
                mma_bf16(o[2*jj+1], pah, &vl[2]);
                mma_bf16(o[2*jj],   pal, &vh[0]);
                mma_bf16(o[2*jj+1], pal, &vh[2]);
            }
        }

        __syncthreads();   // all warps done reading stage s
        if (tile + 2 < Sq/64) { issue_kv(tile + 2, s); cp_commit(); }
    }

    // ---- epilogue: normalize, split to bf16 hi/lo ----
    float inv0 = 1.0f / l0, inv1 = 1.0f / l1;
    const int row0 = q0 + wid*16 + g;
    size_t ob0 = ((size_t)(b*Sq) + row0) * Dq + h*HDq;
    size_t ob1 = ob0 + (size_t)8 * Dq;
    #pragma unroll
    for (int j = 0; j < 8; j++) {
        const int c = j*8 + t4*2;
        float f0 = o[j][0] * inv0, f1 = o[j][1] * inv0;
        float f2 = o[j][2] * inv1, f3 = o[j][3] * inv1;
        __nv_bfloat16 h0 = __float2bfloat16(f0), h1 = __float2bfloat16(f1);
        __nv_bfloat16 h2 = __float2bfloat16(f2), h3 = __float2bfloat16(f3);
        *(__nv_bfloat162*)&Ah[ob0 + c] = __nv_bfloat162(h0, h1);
        *(__nv_bfloat162*)&Ah[ob1 + c] = __nv_bfloat162(h2, h3);
        *(__nv_bfloat162*)&Al[ob0 + c] = __nv_bfloat162(
            __float2bfloat16(f0 - __bfloat162float(h0)),
            __float2bfloat16(f1 - __bfloat162float(h1)));
        *(__nv_bfloat162*)&Al[ob1 + c] = __nv_bfloat162(
            __float2bfloat16(f2 - __bfloat162float(h2)),
            __float2bfloat16(f3 - __bfloat162float(h3)));
    }
}

// ---------------------------------------------------------------------------
extern "C" void kernel_launch(void* const* d_in, const int* in_sizes, int n_in,
                              void* d_out, int out_size)
{
    const float* q   = (const float*)d_in[0];
    const float* k   = (const float*)d_in[1];
    const float* v   = (const float*)d_in[2];
    const float* w_q = (const float*)d_in[3];
    const float* b_q = (const float*)d_in[4];
    const float* w_k = (const float*)d_in[5];
    const float* b_k = (const float*)d_in[6];
    const float* w_v = (const float*)d_in[7];
    const float* b_v = (const float*)d_in[8];
    const float* w_fc= (const float*)d_in[9];
    const float* b_fc= (const float*)d_in[10];
    float* out = (float*)d_out;

    __nv_bfloat16 *xh, *xl, *wh, *wl, *Qh, *Ql, *Kh, *Kl, *Vh, *Vl, *Ahp, *Alp;
    cudaGetSymbolAddress((void**)&xh, g_xh);
    cudaGetSymbolAddress((void**)&xl, g_xl);
    cudaGetSymbolAddress((void**)&wh, g_wh);
    cudaGetSymbolAddress((void**)&wl, g_wl);
    cudaGetSymbolAddress((void**)&Qh, g_Qh);
    cudaGetSymbolAddress((void**)&Ql, g_Ql);
    cudaGetSymbolAddress((void**)&Kh, g_Kh);
    cudaGetSymbolAddress((void**)&Kl, g_Kl);
    cudaGetSymbolAddress((void**)&Vh, g_Vh);
    cudaGetSymbolAddress((void**)&Vl, g_Vl);
    cudaGetSymbolAddress((void**)&Ahp, g_Ah);
    cudaGetSymbolAddress((void**)&Alp, g_Al);

    cudaFuncSetAttribute(gemm_mma_kernel<true>,
                         cudaFuncAttributeMaxDynamicSharedMemorySize, GSMEM);
    cudaFuncSetAttribute(gemm_mma_kernel<false>,
                         cudaFuncAttributeMaxDynamicSharedMemorySize, GSMEM);
    cudaFuncSetAttribute(attn_mma_kernel,
                         cudaFuncAttributeMaxDynamicSharedMemorySize, AT_SMEM);

    const int actN4 = BSq*Dq/4;
    const int wN4   = DD/4;
    dim3 sblk(256);
    dim3 sgrid_act((actN4 + 255)/256);
    dim3 sgrid_w((wN4 + 255)/256);
    dim3 tcgrid(Dq/128, BSq/128);

    // weight splits
    split_kernel<<<sgrid_w, sblk>>>((const float4*)w_q,  (__nv_bfloat162*)(wh + 0*DD), (__nv_bfloat162*)(wl + 0*DD), wN4);
    split_kernel<<<sgrid_w, sblk>>>((const float4*)w_k,  (__nv_bfloat162*)(wh + 1*DD), (__nv_bfloat162*)(wl + 1*DD), wN4);
    split_kernel<<<sgrid_w, sblk>>>((const float4*)w_v,  (__nv_bfloat162*)(wh + 2*DD), (__nv_bfloat162*)(wl + 2*DD), wN4);
    split_kernel<<<sgrid_w, sblk>>>((const float4*)w_fc, (__nv_bfloat162*)(wh + 3*DD), (__nv_bfloat162*)(wl + 3*DD), wN4);

    // projections -> bf16 hi/lo outputs
    split_kernel<<<sgrid_act, sblk>>>((const float4*)q, (__nv_bfloat162*)xh, (__nv_bfloat162*)xl, actN4);
    gemm_mma_kernel<true><<<tcgrid, 256, GSMEM>>>(xh, xl, wh + 0*DD, wl + 0*DD, b_q, nullptr, Qh, Ql);
    split_kernel<<<sgrid_act, sblk>>>((const float4*)k, (__nv_bfloat162*)xh, (__nv_bfloat162*)xl, actN4);
    gemm_mma_kernel<true><<<tcgrid, 256, GSMEM>>>(xh, xl, wh + 1*DD, wl + 1*DD, b_k, nullptr, Kh, Kl);
    split_kernel<<<sgrid_act, sblk>>>((const float4*)v, (__nv_bfloat162*)xh, (__nv_bfloat162*)xl, actN4);
    gemm_mma_kernel<true><<<tcgrid, 256, GSMEM>>>(xh, xl, wh + 2*DD, wl + 2*DD, b_v, nullptr, Vh, Vl);

    // attention (tensor cores, split precision, pipelined KV)
    attn_mma_kernel<<<dim3(Sq/128, Bq*Hq), 256, AT_SMEM>>>(Qh, Ql, Kh, Kl, Vh, Vl, Ahp, Alp);

    // output projection (fp32 out)
    gemm_mma_kernel<false><<<tcgrid, 256, GSMEM>>>(Ahp, Alp, wh + 3*DD, wl + 3*DD, b_fc, out, nullptr, nullptr);
}

// round 6
// speedup vs baseline: 3.4587x; 1.0878x over previous
#include <cuda_runtime.h>
#include <cuda_bf16.h>
#include <cstdint>

#define Bq 4
#define Sq 2048
#define Dq 1024
#define Hq 16
#define HDq 64
#define BSq (Bq*Sq)   // 8192
#define DD  (Dq*Dq)

// ---------------- scratch (__device__ globals; no allocs allowed) ----------
__device__ __nv_bfloat16 g_xh[3*BSq*Dq];
__device__ __nv_bfloat16 g_xl[3*BSq*Dq];
__device__ __nv_bfloat16 g_wh[4*DD];
__device__ __nv_bfloat16 g_wl[4*DD];
__device__ __nv_bfloat16 g_Qh[BSq*Dq];
__device__ __nv_bfloat16 g_Ql[BSq*Dq];
__device__ __nv_bfloat16 g_Kh[BSq*Dq];
__device__ __nv_bfloat16 g_Kl[BSq*Dq];
__device__ __nv_bfloat16 g_Vh[BSq*Dq];
__device__ __nv_bfloat16 g_Vl[BSq*Dq];
__device__ __nv_bfloat16 g_Ah[BSq*Dq];
__device__ __nv_bfloat16 g_Al[BSq*Dq];

__device__ __forceinline__ uint32_t smem_to_u32(const void* p) {
    uint32_t a;
    asm("{ .reg .u64 t; cvta.to.shared.u64 t, %1; cvt.u32.u64 %0, t; }"
        : "=r"(a) : "l"(p));
    return a;
}
__device__ __forceinline__ void cp16(uint32_t dst, const void* src) {
    asm volatile("cp.async.cg.shared.global [%0], [%1], 16;"
                 :: "r"(dst), "l"(src) : "memory");
}
__device__ __forceinline__ void cp_commit() {
    asm volatile("cp.async.commit_group;" ::: "memory");
}
template <int N>
__device__ __forceinline__ void cp_wait() {
    asm volatile("cp.async.wait_group %0;" :: "n"(N) : "memory");
}
__device__ __forceinline__ void ldsm_x4(uint32_t* r, uint32_t addr) {
    asm volatile("ldmatrix.sync.aligned.m8n8.x4.shared.b16 {%0,%1,%2,%3}, [%4];"
                 : "=r"(r[0]), "=r"(r[1]), "=r"(r[2]), "=r"(r[3]) : "r"(addr));
}
__device__ __forceinline__ void ldsm_x4_trans(uint32_t* r, uint32_t addr) {
    asm volatile("ldmatrix.sync.aligned.m8n8.x4.trans.shared.b16 {%0,%1,%2,%3}, [%4];"
                 : "=r"(r[0]), "=r"(r[1]), "=r"(r[2]), "=r"(r[3]) : "r"(addr));
}
__device__ __forceinline__ void mma_bf16(float* d, const uint32_t* a, const uint32_t* b) {
    asm volatile(
        "mma.sync.aligned.m16n8k16.row.col.f32.bf16.bf16.f32 "
        "{%0,%1,%2,%3}, {%4,%5,%6,%7}, {%8,%9}, {%0,%1,%2,%3};"
        : "+f"(d[0]), "+f"(d[1]), "+f"(d[2]), "+f"(d[3])
        : "r"(a[0]), "r"(a[1]), "r"(a[2]), "r"(a[3]), "r"(b[0]), "r"(b[1]));
}
__device__ __forceinline__ uint32_t pack_bf16(float x, float y) {
    __nv_bfloat162 v = __floats2bfloat162_rn(x, y);
    return *(uint32_t*)&v;
}

// ---------------------------------------------------------------------------
// Batched fp32 -> (bf16 hi, bf16 lo) splits
// ---------------------------------------------------------------------------
__device__ __forceinline__ void split_body(const float4* __restrict__ x,
                                           __nv_bfloat162* __restrict__ hi,
                                           __nv_bfloat162* __restrict__ lo, int n4)
{
    int i = blockIdx.x * blockDim.x + threadIdx.x;
    if (i >= n4) return;
    float4 v = x[i];
    __nv_bfloat16 h0 = __float2bfloat16(v.x);
    __nv_bfloat16 h1 = __float2bfloat16(v.y);
    __nv_bfloat16 h2 = __float2bfloat16(v.z);
    __nv_bfloat16 h3 = __float2bfloat16(v.w);
    hi[i*2 + 0] = __nv_bfloat162(h0, h1);
    hi[i*2 + 1] = __nv_bfloat162(h2, h3);
    lo[i*2 + 0] = __nv_bfloat162(
        __float2bfloat16(v.x - __bfloat162float(h0)),
        __float2bfloat16(v.y - __bfloat162float(h1)));
    lo[i*2 + 1] = __nv_bfloat162(
        __float2bfloat16(v.z - __bfloat162float(h2)),
        __float2bfloat16(v.w - __bfloat162float(h3)));
}

__global__ void split_act_kernel(const float4* __restrict__ q, const float4* __restrict__ k,
                                 const float4* __restrict__ v,
                                 __nv_bfloat162* __restrict__ hi,
                                 __nv_bfloat162* __restrict__ lo, int n4)
{
    const int z = blockIdx.y;
    const float4* x = (z == 0) ? q : (z == 1) ? k : v;
    split_body(x, hi + (size_t)z * n4 * 2, lo + (size_t)z * n4 * 2, n4);
}

__global__ void split_w_kernel(const float4* __restrict__ w0, const float4* __restrict__ w1,
                               const float4* __restrict__ w2, const float4* __restrict__ w3,
                               __nv_bfloat162* __restrict__ hi,
                               __nv_bfloat162* __restrict__ lo, int n4)
{
    const int z = blockIdx.y;
    const float4* x = (z == 0) ? w0 : (z == 1) ? w1 : (z == 2) ? w2 : w3;
    split_body(x, hi + (size_t)z * n4 * 2, lo + (size_t)z * n4 * 2, n4);
}

// ---------------------------------------------------------------------------
// HMMA split-GEMM, batched over blockIdx.z (matrix/bias/output select).
// CTA 128x128, 8 warps (warp tile 64x32), K-chunk 32, 2-stage cp.async.
// ---------------------------------------------------------------------------
#define GSTRIDE 40
#define GMAT    (128*GSTRIDE*2)
#define GSTAGE  (4*GMAT)
#define GSMEM   (2*GSTAGE)
#define NCHUNK  (Dq/32)

template<bool SPLIT>
__global__ __launch_bounds__(256, 2)
void gemm_mma_kernel(const __nv_bfloat16* __restrict__ Ahb,
                     const __nv_bfloat16* __restrict__ Alb,
                     const __nv_bfloat16* __restrict__ Whb,
                     const __nv_bfloat16* __restrict__ Wlb,
                     const float* __restrict__ bias0, const float* __restrict__ bias1,
                     const float* __restrict__ bias2,
                     float* __restrict__ C,
                     __nv_bfloat16* __restrict__ Ch0, __nv_bfloat16* __restrict__ Cl0,
                     __nv_bfloat16* __restrict__ Ch1, __nv_bfloat16* __restrict__ Cl1,
                     __nv_bfloat16* __restrict__ Ch2, __nv_bfloat16* __restrict__ Cl2)
{
    extern __shared__ char smem[];
    const uint32_t smem_base = smem_to_u32(smem);
    const int tid  = threadIdx.x;
    const int lane = tid & 31;
    const int wid  = tid >> 5;
    const int z  = blockIdx.z;
    const int m0 = blockIdx.y * 128;
    const int n0 = blockIdx.x * 128;
    const int wm0 = (wid & 1) * 64;
    const int wn0 = (wid >> 1) * 32;

    const float* bias = (z == 0) ? bias0 : (z == 1) ? bias1 : bias2;
    __nv_bfloat16* Ch = (z == 0) ? Ch0 : (z == 1) ? Ch1 : Ch2;
    __nv_bfloat16* Cl = (z == 0) ? Cl0 : (z == 1) ? Cl1 : Cl2;

    const int id0 = tid, id1 = tid + 256;
    const int row0 = id0 >> 2, kq0 = (id0 & 3) * 8;
    const int row1 = id1 >> 2, kq1 = (id1 & 3) * 8;

    const __nv_bfloat16* gAh = Ahb + (size_t)z * BSq * Dq + (size_t)m0 * Dq;
    const __nv_bfloat16* gAl = Alb + (size_t)z * BSq * Dq + (size_t)m0 * Dq;
    const __nv_bfloat16* gWh = Whb + (size_t)z * DD + (size_t)n0 * Dq;
    const __nv_bfloat16* gWl = Wlb + (size_t)z * DD + (size_t)n0 * Dq;

    float acc[4][4][4];
    #pragma unroll
    for (int i = 0; i < 4; i++)
        #pragma unroll
        for (int j = 0; j < 4; j++)
            #pragma unroll
            for (int r = 0; r < 4; r++) acc[i][j][r] = 0.f;

    auto issue = [&](int c, int s) {
        const int k0 = c * 32;
        uint32_t sb = smem_base + s * GSTAGE;
        uint32_t d0 = (uint32_t)(row0 * (GSTRIDE*2) + kq0 * 2);
        uint32_t d1 = (uint32_t)(row1 * (GSTRIDE*2) + kq1 * 2);
        size_t s0 = (size_t)row0 * Dq + k0 + kq0;
        size_t s1 = (size_t)row1 * Dq + k0 + kq1;
        cp16(sb + 0*GMAT + d0, gAh + s0);
        cp16(sb + 0*GMAT + d1, gAh + s1);
        cp16(sb + 1*GMAT + d0, gAl + s0);
        cp16(sb + 1*GMAT + d1, gAl + s1);
        cp16(sb + 2*GMAT + d0, gWh + s0);
        cp16(sb + 2*GMAT + d1, gWh + s1);
        cp16(sb + 3*GMAT + d0, gWl + s0);
        cp16(sb + 3*GMAT + d1, gWl + s1);
    };

    issue(0, 0);
    cp_commit();

    const int a_r = wm0 + (lane & 15);
    const int a_c = (lane >> 4) * 8;
    const int b_r = wn0 + (lane & 7) + ((lane >> 4) << 3);
    const int b_c = ((lane >> 3) & 1) * 8;

    for (int c = 0; c < NCHUNK; c++) {
        const int s = c & 1;
        if (c + 1 < NCHUNK) { issue(c + 1, s ^ 1); cp_commit(); }
        if (c + 1 < NCHUNK) cp_wait<1>(); else cp_wait<0>();
        __syncthreads();

        const uint32_t sb = smem_base + s * GSTAGE;
        const uint32_t aH = sb + 0*GMAT, aL = sb + 1*GMAT;
        const uint32_t wH = sb + 2*GMAT, wL = sb + 3*GMAT;

        #pragma unroll
        for (int kk = 0; kk < 2; kk++) {
            const int k16 = kk * 16;
            uint32_t bh[2][4], bl[2][4];
            #pragma unroll
            for (int jj = 0; jj < 2; jj++) {
                uint32_t off = (uint32_t)((b_r + jj*16) * (GSTRIDE*2) + (k16 + b_c) * 2);
                ldsm_x4(bh[jj], wH + off);
                ldsm_x4(bl[jj], wL + off);
            }
            #pragma unroll
            for (int i = 0; i < 4; i++) {
                uint32_t ah[4], al[4];
                uint32_t off = (uint32_t)((a_r + i*16) * (GSTRIDE*2) + (k16 + a_c) * 2);
                ldsm_x4(ah, aH + off);
                ldsm_x4(al, aL + off);
                #pragma unroll
                for (int j = 0; j < 4; j++) {
                    const uint32_t* bhp = &bh[j >> 1][(j & 1) * 2];
                    const uint32_t* blp = &bl[j >> 1][(j & 1) * 2];
                    mma_bf16(acc[i][j], ah, bhp);
                    mma_bf16(acc[i][j], ah, blp);
                    mma_bf16(acc[i][j], al, bhp);
                }
            }
        }
        __syncthreads();
    }

    // epilogue
    const int g = lane >> 2, t = lane & 3;
    #pragma unroll
    for (int j = 0; j < 4; j++) {
        const int col = n0 + wn0 + j*8 + t*2;
        const float bx = __ldg(&bias[col]);
        const float by = __ldg(&bias[col + 1]);
        #pragma unroll
        for (int i = 0; i < 4; i++) {
            const int r0 = m0 + wm0 + i*16 + g;
            float v0x = acc[i][j][0] + bx, v0y = acc[i][j][1] + by;
            float v1x = acc[i][j][2] + bx, v1y = acc[i][j][3] + by;
            if (SPLIT) {
                __nv_bfloat16 h0x = __float2bfloat16(v0x), h0y = __float2bfloat16(v0y);
                __nv_bfloat16 h1x = __float2bfloat16(v1x), h1y = __float2bfloat16(v1y);
                *(__nv_bfloat162*)&Ch[(size_t)r0 * Dq + col] = __nv_bfloat162(h0x, h0y);
                *(__nv_bfloat162*)&Ch[(size_t)(r0+8) * Dq + col] = __nv_bfloat162(h1x, h1y);
                *(__nv_bfloat162*)&Cl[(size_t)r0 * Dq + col] = __nv_bfloat162(
                    __float2bfloat16(v0x - __bfloat162float(h0x)),
                    __float2bfloat16(v0y - __bfloat162float(h0y)));
                *(__nv_bfloat162*)&Cl[(size_t)(r0+8) * Dq + col] = __nv_bfloat162(
                    __float2bfloat16(v1x - __bfloat162float(h1x)),
                    __float2bfloat16(v1y - __bfloat162float(h1y)));
            } else {
                float2 w0, w1;
                w0.x = v0x; w0.y = v0y; w1.x = v1x; w1.y = v1y;
                *(float2*)&C[(size_t)r0 * Dq + col] = w0;
                *(float2*)&C[(size_t)(r0 + 8) * Dq + col] = w1;
            }
        }
    }
}

// ---------------------------------------------------------------------------
// FA2-style HMMA attention, 2-stage cp.async KV pipeline, Q smem-resident
// (fragments reloaded per tile -> low register pressure, true occ=2).
// smem: [0,36864) Q hi/lo; [36864, 36864+73728) 2 KV stages.
// ---------------------------------------------------------------------------
#define AST 72
#define AT_TILE  (64*AST*2)          // 9216 B
#define AT_STAGE (4*AT_TILE)         // 36864 B
#define QBYTES   (128*AST*2)         // 18432 B per Q matrix
#define QLOFF    QBYTES
#define KVOFF    (2*QBYTES)          // 36864
#define AT_SMEM  (KVOFF + 2*AT_STAGE)  // 110592 B

__global__ __launch_bounds__(256, 2)
void attn_mma_kernel(const __nv_bfloat16* __restrict__ Qh, const __nv_bfloat16* __restrict__ Ql,
                     const __nv_bfloat16* __restrict__ Kh, const __nv_bfloat16* __restrict__ Kl,
                     const __nv_bfloat16* __restrict__ Vh, const __nv_bfloat16* __restrict__ Vl,
                     __nv_bfloat16* __restrict__ Ah, __nv_bfloat16* __restrict__ Al)
{
    extern __shared__ char smem[];
    const uint32_t sbase = smem_to_u32(smem);
    const int tid = threadIdx.x, lane = tid & 31, wid = tid >> 5;
    const int bh = blockIdx.y, b = bh >> 4, h = bh & 15;
    const int q0 = blockIdx.x * 128;
    const int g = lane >> 2, t4 = lane & 3;

    // ---- stage Q (scaled by 1/8, exact in bf16); persists whole kernel ----
    {
        __nv_bfloat16* sQh = (__nv_bfloat16*)smem;
        __nv_bfloat16* sQl = sQh + 128*AST;
        const int row = tid >> 1, halfo = (tid & 1) * 32;
        const __nv_bfloat162 sc = __floats2bfloat162_rn(0.125f, 0.125f);
        size_t gq = ((size_t)(b*Sq) + q0 + row) * Dq + h*HDq + halfo;
        #pragma unroll
        for (int u = 0; u < 4; u++) {
            uint4 xh4 = *(const uint4*)(Qh + gq + u*8);
            uint4 xl4 = *(const uint4*)(Ql + gq + u*8);
            __nv_bfloat162* ph = (__nv_bfloat162*)&xh4;
            __nv_bfloat162* pl = (__nv_bfloat162*)&xl4;
            #pragma unroll
            for (int e = 0; e < 4; e++) { ph[e] = __hmul2(ph[e], sc); pl[e] = __hmul2(pl[e], sc); }
            *(uint4*)&sQh[row*AST + halfo + u*8] = xh4;
            *(uint4*)&sQl[row*AST + halfo + u*8] = xl4;
        }
    }

    // KV cp.async issue: each thread 8 x cp16 (2 per matrix)
    const int krow = tid >> 2, kd0 = (tid & 3) * 16;
    const size_t kvrowbase = (size_t)(b*Sq) * Dq + h*HDq + (size_t)krow * Dq + kd0;
    const uint32_t so = (uint32_t)((krow*AST + kd0) * 2);

    auto issue_kv = [&](int tile, int s) {
        size_t gk = kvrowbase + (size_t)tile * 64 * Dq;
        uint32_t sb = sbase + KVOFF + s * AT_STAGE;
        cp16(sb + 0*AT_TILE + so,      Kh + gk);
        cp16(sb + 0*AT_TILE + so + 16, Kh + gk + 8);
        cp16(sb + 1*AT_TILE + so,      Kl + gk);
        cp16(sb + 1*AT_TILE + so + 16, Kl + gk + 8);
        cp16(sb + 2*AT_TILE + so,      Vh + gk);
        cp16(sb + 2*AT_TILE + so + 16, Vh + gk + 8);
        cp16(sb + 3*AT_TILE + so,      Vl + gk);
        cp16(sb + 3*AT_TILE + so + 16, Vl + gk + 8);
    };

    issue_kv(0, 0); cp_commit();
    issue_kv(1, 1); cp_commit();
    __syncthreads();   // Q staged (also orders smem Q writes vs ldsm reads)

    const uint32_t q_rowoff = (uint32_t)(((wid*16 + (lane & 15))*AST + (lane >> 4)*8) * 2);

    float m0 = -1e30f, m1 = -1e30f, l0 = 0.f, l1 = 0.f;
    float o[8][4];
    #pragma unroll
    for (int j = 0; j < 8; j++)
        #pragma unroll
        for (int r = 0; r < 4; r++) o[j][r] = 0.f;

    const uint32_t kb_row = (lane & 7) + ((lane >> 4) & 1) * 8;
    const uint32_t kb_col = ((lane >> 3) & 1) * 8;
    const uint32_t vb_row = (lane & 7) + ((lane >> 3) & 1) * 8;
    const uint32_t vb_col = ((lane >> 4) & 1) * 8;

    for (int tile = 0; tile < Sq/64; tile++) {
        const int s = tile & 1;
        const uint32_t sb = sbase + KVOFF + s * AT_STAGE;
        const uint32_t oKh = sb, oKl = sb + AT_TILE, oVh = sb + 2*AT_TILE, oVl = sb + 3*AT_TILE;

        cp_wait<1>();
        __syncthreads();

        // ---- S = (Q/8) K^T, 3 split terms; Q frags reloaded from smem ----
        float sAcc[8][4];
        #pragma unroll
        for (int j = 0; j < 8; j++)
            #pragma unroll
            for (int r = 0; r < 4; r++) sAcc[j][r] = 0.f;
        #pragma unroll
        for (int kk = 0; kk < 4; kk++) {
            uint32_t qh[4], ql[4];
            ldsm_x4(qh, sbase + q_rowoff + kk*32);
            ldsm_x4(ql, sbase + QLOFF + q_rowoff + kk*32);
            #pragma unroll
            for (int jj = 0; jj < 4; jj++) {
                uint32_t off = (uint32_t)(((jj*16 + kb_row)*AST + kk*16 + kb_col) * 2);
                uint32_t kf[4], lf[4];
                ldsm_x4(kf, oKh + off);
                ldsm_x4(lf, oKl + off);
                mma_bf16(sAcc[2*jj],   qh, &kf[0]);
                mma_bf16(sAcc[2*jj+1], qh, &kf[2]);
                mma_bf16(sAcc[2*jj],   qh, &lf[0]);
                mma_bf16(sAcc[2*jj+1], qh, &lf[2]);
                mma_bf16(sAcc[2*jj],   ql, &kf[0]);
                mma_bf16(sAcc[2*jj+1], ql, &kf[2]);
            }
        }

        // ---- online softmax ----
        float mx0 = -1e30f, mx1 = -1e30f;
        #pragma unroll
        for (int j = 0; j < 8; j++) {
            mx0 = fmaxf(mx0, fmaxf(sAcc[j][0], sAcc[j][1]));
            mx1 = fmaxf(mx1, fmaxf(sAcc[j][2], sAcc[j][3]));
        }
        mx0 = fmaxf(mx0, __shfl_xor_sync(0xffffffffu, mx0, 1));
        mx0 = fmaxf(mx0, __shfl_xor_sync(0xffffffffu, mx0, 2));
        mx1 = fmaxf(mx1, __shfl_xor_sync(0xffffffffu, mx1, 1));
        mx1 = fmaxf(mx1, __shfl_xor_sync(0xffffffffu, mx1, 2));
        float mn0 = fmaxf(m0, mx0), mn1 = fmaxf(m1, mx1);
        float c0 = __expf(m0 - mn0), c1 = __expf(m1 - mn1);
        float sum0 = 0.f, sum1 = 0.f;
        #pragma unroll
        for (int j = 0; j < 8; j++) {
            sAcc[j][0] = __expf(sAcc[j][0] - mn0); sum0 += sAcc[j][0];
            sAcc[j][1] = __expf(sAcc[j][1] - mn0); sum0 += sAcc[j][1];
            sAcc[j][2] = __expf(sAcc[j][2] - mn1); sum1 += sAcc[j][2];
            sAcc[j][3] = __expf(sAcc[j][3] - mn1); sum1 += sAcc[j][3];
        }
        sum0 += __shfl_xor_sync(0xffffffffu, sum0, 1);
        sum0 += __shfl_xor_sync(0xffffffffu, sum0, 2);
        sum1 += __shfl_xor_sync(0xffffffffu, sum1, 1);
        sum1 += __shfl_xor_sync(0xffffffffu, sum1, 2);
        m0 = mn0; m1 = mn1;
        l0 = l0 * c0 + sum0;
        l1 = l1 * c1 + sum1;
        #pragma unroll
        for (int j = 0; j < 8; j++) {
            o[j][0] *= c0; o[j][1] *= c0;
            o[j][2] *= c1; o[j][3] *= c1;
        }

        // ---- O += P V, 3 split terms ----
        #pragma unroll
        for (int kk = 0; kk < 4; kk++) {
            uint32_t pah[4], pal[4];
            {
                float* s0 = sAcc[2*kk];
                float* s1 = sAcc[2*kk+1];
                pah[0] = pack_bf16(s0[0], s0[1]);
                pah[1] = pack_bf16(s0[2], s0[3]);
                pah[2] = pack_bf16(s1[0], s1[1]);
                pah[3] = pack_bf16(s1[2], s1[3]);
                __nv_bfloat162 hh;
                hh = *(__nv_bfloat162*)&pah[0];
                pal[0] = pack_bf16(s0[0] - __bfloat162float(hh.x), s0[1] - __bfloat162float(hh.y));
                hh = *(__nv_bfloat162*)&pah[1];
                pal[1] = pack_bf16(s0[2] - __bfloat162float(hh.x), s0[3] - __bfloat162float(hh.y));
                hh = *(__nv_bfloat162*)&pah[2];
                pal[2] = pack_bf16(s1[0] - __bfloat162float(hh.x), s1[1] - __bfloat162float(hh.y));
                hh = *(__nv_bfloat162*)&pah[3];
                pal[3] = pack_bf16(s1[2] - __bfloat162float(hh.x), s1[3] - __bfloat162float(hh.y));
            }
            #pragma unroll
            for (int jj = 0; jj < 4; jj++) {
                uint32_t off = (uint32_t)(((kk*16 + vb_row)*AST + jj*16 + vb_col) * 2);
                uint32_t vh[4], vl[4];
                ldsm_x4_trans(vh, oVh + off);
                ldsm_x4_trans(vl, oVl + off);
                mma_bf16(o[2*jj],   pah, &vh[0]);
                mma_bf16(o[2*jj+1], pah, &vh[2]);
                mma_bf16(o[2*jj],   pah, &vl[0]);
                mma_bf16(o[2*jj+1], pah, &vl[2]);
                mma_bf16(o[2*jj],   pal, &vh[0]);
                mma_bf16(o[2*jj+1], pal, &vh[2]);
            }
        }

        __syncthreads();
        if (tile + 2 < Sq/64) { issue_kv(tile + 2, s); cp_commit(); }
    }

    // ---- epilogue: normalize, split to bf16 hi/lo ----
    float inv0 = 1.0f / l0, inv1 = 1.0f / l1;
    const int row0 = q0 + wid*16 + g;
    size_t ob0 = ((size_t)(b*Sq) + row0) * Dq + h*HDq;
    size_t ob1 = ob0 + (size_t)8 * Dq;
    #pragma unroll
    for (int j = 0; j < 8; j++) {
        const int c = j*8 + t4*2;
        float f0 = o[j][0] * inv0, f1 = o[j][1] * inv0;
        float f2 = o[j][2] * inv1, f3 = o[j][3] * inv1;
        __nv_bfloat16 h0 = __float2bfloat16(f0), h1 = __float2bfloat16(f1);
        __nv_bfloat16 h2 = __float2bfloat16(f2), h3 = __float2bfloat16(f3);
        *(__nv_bfloat162*)&Ah[ob0 + c] = __nv_bfloat162(h0, h1);
        *(__nv_bfloat162*)&Ah[ob1 + c] = __nv_bfloat162(h2, h3);
        *(__nv_bfloat162*)&Al[ob0 + c] = __nv_bfloat162(
            __float2bfloat16(f0 - __bfloat162float(h0)),
            __float2bfloat16(f1 - __bfloat162float(h1)));
        *(__nv_bfloat162*)&Al[ob1 + c] = __nv_bfloat162(
            __float2bfloat16(f2 - __bfloat162float(h2)),
            __float2bfloat16(f3 - __bfloat162float(h3)));
    }
}

// ---------------------------------------------------------------------------
extern "C" void kernel_launch(void* const* d_in, const int* in_sizes, int n_in,
                              void* d_out, int out_size)
{
    const float* q   = (const float*)d_in[0];
    const float* k   = (const float*)d_in[1];
    const float* v   = (const float*)d_in[2];
    const float* w_q = (const float*)d_in[3];
    const float* b_q = (const float*)d_in[4];
    const float* w_k = (const float*)d_in[5];
    const float* b_k = (const float*)d_in[6];
    const float* w_v = (const float*)d_in[7];
    const float* b_v = (const float*)d_in[8];
    const float* w_fc= (const float*)d_in[9];
    const float* b_fc= (const float*)d_in[10];
    float* out = (float*)d_out;

    __nv_bfloat16 *xh, *xl, *wh, *wl, *Qh, *Ql, *Kh, *Kl, *Vh, *Vl, *Ahp, *Alp;
    cudaGetSymbolAddress((void**)&xh, g_xh);
    cudaGetSymbolAddress((void**)&xl, g_xl);
    cudaGetSymbolAddress((void**)&wh, g_wh);
    cudaGetSymbolAddress((void**)&wl, g_wl);
    cudaGetSymbolAddress((void**)&Qh, g_Qh);
    cudaGetSymbolAddress((void**)&Ql, g_Ql);
    cudaGetSymbolAddress((void**)&Kh, g_Kh);
    cudaGetSymbolAddress((void**)&Kl, g_Kl);
    cudaGetSymbolAddress((void**)&Vh, g_Vh);
    cudaGetSymbolAddress((void**)&Vl, g_Vl);
    cudaGetSymbolAddress((void**)&Ahp, g_Ah);
    cudaGetSymbolAddress((void**)&Alp, g_Al);

    cudaFuncSetAttribute(gemm_mma_kernel<true>,
                         cudaFuncAttributeMaxDynamicSharedMemorySize, GSMEM);
    cudaFuncSetAttribute(gemm_mma_kernel<false>,
                         cudaFuncAttributeMaxDynamicSharedMemorySize, GSMEM);
    cudaFuncSetAttribute(attn_mma_kernel,
                         cudaFuncAttributeMaxDynamicSharedMemorySize, AT_SMEM);

    const int actN4 = BSq*Dq/4;
    const int wN4   = DD/4;
    dim3 sblk(256);

    // all 4 weight splits, one launch
    split_w_kernel<<<dim3((wN4 + 255)/256, 4), sblk>>>(
        (const float4*)w_q, (const float4*)w_k, (const float4*)w_v, (const float4*)w_fc,
        (__nv_bfloat162*)wh, (__nv_bfloat162*)wl, wN4);

    // all 3 activation splits, one launch
    split_act_kernel<<<dim3((actN4 + 255)/256, 3), sblk>>>(
        (const float4*)q, (const float4*)k, (const float4*)v,
        (__nv_bfloat162*)xh, (__nv_bfloat162*)xl, actN4);

    // Q/K/V projections, one launch (grid.z selects matrix)
    gemm_mma_kernel<true><<<dim3(Dq/128, BSq/128, 3), 256, GSMEM>>>(
        xh, xl, wh, wl, b_q, b_k, b_v, nullptr,
        Qh, Ql, Kh, Kl, Vh, Vl);

    // attention (tensor cores, split precision, pipelined KV, occ=2)
    attn_mma_kernel<<<dim3(Sq/128, Bq*Hq), 256, AT_SMEM>>>(Qh, Ql, Kh, Kl, Vh, Vl, Ahp, Alp);

    // output projection (fp32 out)
    gemm_mma_kernel<false><<<dim3(Dq/128, BSq/128, 1), 256, GSMEM>>>(
        Ahp, Alp, wh + 3*DD, wl + 3*DD, b_fc, b_fc, b_fc, out,
        nullptr, nullptr, nullptr, nullptr, nullptr, nullptr);
}

// round 7
// speedup vs baseline: 3.4702x; 1.0033x over previous
#include <cuda_runtime.h>
#include <cuda_bf16.h>
#include <cstdint>

#define Bq 4
#define Sq 2048
#define Dq 1024
#define Hq 16
#define HDq 64
#define BSq (Bq*Sq)   // 8192
#define DD  (Dq*Dq)

// ---------------- scratch (__device__ globals; no allocs allowed) ----------
__device__ __nv_bfloat16 g_xh[3*BSq*Dq];
__device__ __nv_bfloat16 g_xl[3*BSq*Dq];
__device__ __nv_bfloat16 g_wh[4*DD];
__device__ __nv_bfloat16 g_wl[4*DD];
__device__ __nv_bfloat16 g_Qh[BSq*Dq];
__device__ __nv_bfloat16 g_Ql[BSq*Dq];
__device__ __nv_bfloat16 g_Kh[BSq*Dq];
__device__ __nv_bfloat16 g_Kl[BSq*Dq];
__device__ __nv_bfloat16 g_Vh[BSq*Dq];
__device__ __nv_bfloat16 g_Vl[BSq*Dq];
__device__ __nv_bfloat16 g_Ah[BSq*Dq];
__device__ __nv_bfloat16 g_Al[BSq*Dq];

__device__ __forceinline__ uint32_t smem_to_u32(const void* p) {
    uint32_t a;
    asm("{ .reg .u64 t; cvta.to.shared.u64 t, %1; cvt.u32.u64 %0, t; }"
        : "=r"(a) : "l"(p));
    return a;
}
__device__ __forceinline__ void cp16(uint32_t dst, const void* src) {
    asm volatile("cp.async.cg.shared.global [%0], [%1], 16;"
                 :: "r"(dst), "l"(src) : "memory");
}
__device__ __forceinline__ void cp_commit() {
    asm volatile("cp.async.commit_group;" ::: "memory");
}
template <int N>
__device__ __forceinline__ void cp_wait() {
    asm volatile("cp.async.wait_group %0;" :: "n"(N) : "memory");
}
__device__ __forceinline__ void ldsm_x4(uint32_t* r, uint32_t addr) {
    asm volatile("ldmatrix.sync.aligned.m8n8.x4.shared.b16 {%0,%1,%2,%3}, [%4];"
                 : "=r"(r[0]), "=r"(r[1]), "=r"(r[2]), "=r"(r[3]) : "r"(addr));
}
__device__ __forceinline__ void ldsm_x4_trans(uint32_t* r, uint32_t addr) {
    asm volatile("ldmatrix.sync.aligned.m8n8.x4.trans.shared.b16 {%0,%1,%2,%3}, [%4];"
                 : "=r"(r[0]), "=r"(r[1]), "=r"(r[2]), "=r"(r[3]) : "r"(addr));
}
__device__ __forceinline__ void mma_bf16(float* d, const uint32_t* a, const uint32_t* b) {
    asm volatile(
        "mma.sync.aligned.m16n8k16.row.col.f32.bf16.bf16.f32 "
        "{%0,%1,%2,%3}, {%4,%5,%6,%7}, {%8,%9}, {%0,%1,%2,%3};"
        : "+f"(d[0]), "+f"(d[1]), "+f"(d[2]), "+f"(d[3])
        : "r"(a[0]), "r"(a[1]), "r"(a[2]), "r"(a[3]), "r"(b[0]), "r"(b[1]));
}
__device__ __forceinline__ uint32_t pack_bf16(float x, float y) {
    __nv_bfloat162 v = __floats2bfloat162_rn(x, y);
    return *(uint32_t*)&v;
}

// ---------------------------------------------------------------------------
// Batched fp32 -> (bf16 hi, bf16 lo) splits
// ---------------------------------------------------------------------------
__device__ __forceinline__ void split_body(const float4* __restrict__ x,
                                           __nv_bfloat162* __restrict__ hi,
                                           __nv_bfloat162* __restrict__ lo, int n4)
{
    int i = blockIdx.x * blockDim.x + threadIdx.x;
    if (i >= n4) return;
    float4 v = x[i];
    __nv_bfloat16 h0 = __float2bfloat16(v.x);
    __nv_bfloat16 h1 = __float2bfloat16(v.y);
    __nv_bfloat16 h2 = __float2bfloat16(v.z);
    __nv_bfloat16 h3 = __float2bfloat16(v.w);
    hi[i*2 + 0] = __nv_bfloat162(h0, h1);
    hi[i*2 + 1] = __nv_bfloat162(h2, h3);
    lo[i*2 + 0] = __nv_bfloat162(
        __float2bfloat16(v.x - __bfloat162float(h0)),
        __float2bfloat16(v.y - __bfloat162float(h1)));
    lo[i*2 + 1] = __nv_bfloat162(
        __float2bfloat16(v.z - __bfloat162float(h2)),
        __float2bfloat16(v.w - __bfloat162float(h3)));
}

__global__ void split_act_kernel(const float4* __restrict__ q, const float4* __restrict__ k,
                                 const float4* __restrict__ v,
                                 __nv_bfloat162* __restrict__ hi,
                                 __nv_bfloat162* __restrict__ lo, int n4)
{
    const int z = blockIdx.y;
    const float4* x = (z == 0) ? q : (z == 1) ? k : v;
    split_body(x, hi + (size_t)z * n4 * 2, lo + (size_t)z * n4 * 2, n4);
}

__global__ void split_w_kernel(const float4* __restrict__ w0, const float4* __restrict__ w1,
                               const float4* __restrict__ w2, const float4* __restrict__ w3,
                               __nv_bfloat162* __restrict__ hi,
                               __nv_bfloat162* __restrict__ lo, int n4)
{
    const int z = blockIdx.y;
    const float4* x = (z == 0) ? w0 : (z == 1) ? w1 : (z == 2) ? w2 : w3;
    split_body(x, hi + (size_t)z * n4 * 2, lo + (size_t)z * n4 * 2, n4);
}

// ---------------------------------------------------------------------------
// HMMA split-GEMM, batched over blockIdx.z (matrix/bias/output select).
// CTA 128x128, 8 warps (warp tile 64x32), K-chunk 32, 2-stage cp.async.
// ---------------------------------------------------------------------------
#define GSTRIDE 40
#define GMAT    (128*GSTRIDE*2)
#define GSTAGE  (4*GMAT)
#define GSMEM   (2*GSTAGE)
#define NCHUNK  (Dq/32)

template<bool SPLIT>
__global__ __launch_bounds__(256, 2)
void gemm_mma_kernel(const __nv_bfloat16* __restrict__ Ahb,
                     const __nv_bfloat16* __restrict__ Alb,
                     const __nv_bfloat16* __restrict__ Whb,
                     const __nv_bfloat16* __restrict__ Wlb,
                     const float* __restrict__ bias0, const float* __restrict__ bias1,
                     const float* __restrict__ bias2,
                     float* __restrict__ C,
                     __nv_bfloat16* __restrict__ Ch0, __nv_bfloat16* __restrict__ Cl0,
                     __nv_bfloat16* __restrict__ Ch1, __nv_bfloat16* __restrict__ Cl1,
                     __nv_bfloat16* __restrict__ Ch2, __nv_bfloat16* __restrict__ Cl2)
{
    extern __shared__ char smem[];
    const uint32_t smem_base = smem_to_u32(smem);
    const int tid  = threadIdx.x;
    const int lane = tid & 31;
    const int wid  = tid >> 5;
    const int z  = blockIdx.z;
    const int m0 = blockIdx.y * 128;
    const int n0 = blockIdx.x * 128;
    const int wm0 = (wid & 1) * 64;
    const int wn0 = (wid >> 1) * 32;

    const float* bias = (z == 0) ? bias0 : (z == 1) ? bias1 : bias2;
    __nv_bfloat16* Ch = (z == 0) ? Ch0 : (z == 1) ? Ch1 : Ch2;
    __nv_bfloat16* Cl = (z == 0) ? Cl0 : (z == 1) ? Cl1 : Cl2;

    const int id0 = tid, id1 = tid + 256;
    const int row0 = id0 >> 2, kq0 = (id0 & 3) * 8;
    const int row1 = id1 >> 2, kq1 = (id1 & 3) * 8;

    const __nv_bfloat16* gAh = Ahb + (size_t)z * BSq * Dq + (size_t)m0 * Dq;
    const __nv_bfloat16* gAl = Alb + (size_t)z * BSq * Dq + (size_t)m0 * Dq;
    const __nv_bfloat16* gWh = Whb + (size_t)z * DD + (size_t)n0 * Dq;
    const __nv_bfloat16* gWl = Wlb + (size_t)z * DD + (size_t)n0 * Dq;

    float acc[4][4][4];
    #pragma unroll
    for (int i = 0; i < 4; i++)
        #pragma unroll
        for (int j = 0; j < 4; j++)
            #pragma unroll
            for (int r = 0; r < 4; r++) acc[i][j][r] = 0.f;

    auto issue = [&](int c, int s) {
        const int k0 = c * 32;
        uint32_t sb = smem_base + s * GSTAGE;
        uint32_t d0 = (uint32_t)(row0 * (GSTRIDE*2) + kq0 * 2);
        uint32_t d1 = (uint32_t)(row1 * (GSTRIDE*2) + kq1 * 2);
        size_t s0 = (size_t)row0 * Dq + k0 + kq0;
        size_t s1 = (size_t)row1 * Dq + k0 + kq1;
        cp16(sb + 0*GMAT + d0, gAh + s0);
        cp16(sb + 0*GMAT + d1, gAh + s1);
        cp16(sb + 1*GMAT + d0, gAl + s0);
        cp16(sb + 1*GMAT + d1, gAl + s1);
        cp16(sb + 2*GMAT + d0, gWh + s0);
        cp16(sb + 2*GMAT + d1, gWh + s1);
        cp16(sb + 3*GMAT + d0, gWl + s0);
        cp16(sb + 3*GMAT + d1, gWl + s1);
    };

    issue(0, 0);
    cp_commit();

    const int a_r = wm0 + (lane & 15);
    const int a_c = (lane >> 4) * 8;
    const int b_r = wn0 + (lane & 7) + ((lane >> 4) << 3);
    const int b_c = ((lane >> 3) & 1) * 8;

    for (int c = 0; c < NCHUNK; c++) {
        const int s = c & 1;
        if (c + 1 < NCHUNK) { issue(c + 1, s ^ 1); cp_commit(); }
        if (c + 1 < NCHUNK) cp_wait<1>(); else cp_wait<0>();
        __syncthreads();

        const uint32_t sb = smem_base + s * GSTAGE;
        const uint32_t aH = sb + 0*GMAT, aL = sb + 1*GMAT;
        const uint32_t wH = sb + 2*GMAT, wL = sb + 3*GMAT;

        #pragma unroll
        for (int kk = 0; kk < 2; kk++) {
            const int k16 = kk * 16;
            uint32_t bh[2][4], bl[2][4];
            #pragma unroll
            for (int jj = 0; jj < 2; jj++) {
                uint32_t off = (uint32_t)((b_r + jj*16) * (GSTRIDE*2) + (k16 + b_c) * 2);
                ldsm_x4(bh[jj], wH + off);
                ldsm_x4(bl[jj], wL + off);
            }
            #pragma unroll
            for (int i = 0; i < 4; i++) {
                uint32_t ah[4], al[4];
                uint32_t off = (uint32_t)((a_r + i*16) * (GSTRIDE*2) + (k16 + a_c) * 2);
                ldsm_x4(ah, aH + off);
                ldsm_x4(al, aL + off);
                #pragma unroll
                for (int j = 0; j < 4; j++) {
                    const uint32_t* bhp = &bh[j >> 1][(j & 1) * 2];
                    const uint32_t* blp = &bl[j >> 1][(j & 1) * 2];
                    mma_bf16(acc[i][j], ah, bhp);
                    mma_bf16(acc[i][j], ah, blp);
                    mma_bf16(acc[i][j], al, bhp);
                }
            }
        }
        __syncthreads();
    }

    // epilogue
    const int g = lane >> 2, t = lane & 3;
    #pragma unroll
    for (int j = 0; j < 4; j++) {
        const int col = n0 + wn0 + j*8 + t*2;
        const float bx = __ldg(&bias[col]);
        const float by = __ldg(&bias[col + 1]);
        #pragma unroll
        for (int i = 0; i < 4; i++) {
            const int r0 = m0 + wm0 + i*16 + g;
            float v0x = acc[i][j][0] + bx, v0y = acc[i][j][1] + by;
            float v1x = acc[i][j][2] + bx, v1y = acc[i][j][3] + by;
            if (SPLIT) {
                __nv_bfloat16 h0x = __float2bfloat16(v0x), h0y = __float2bfloat16(v0y);
                __nv_bfloat16 h1x = __float2bfloat16(v1x), h1y = __float2bfloat16(v1y);
                *(__nv_bfloat162*)&Ch[(size_t)r0 * Dq + col] = __nv_bfloat162(h0x, h0y);
                *(__nv_bfloat162*)&Ch[(size_t)(r0+8) * Dq + col] = __nv_bfloat162(h1x, h1y);
                *(__nv_bfloat162*)&Cl[(size_t)r0 * Dq + col] = __nv_bfloat162(
                    __float2bfloat16(v0x - __bfloat162float(h0x)),
                    __float2bfloat16(v0y - __bfloat162float(h0y)));
                *(__nv_bfloat162*)&Cl[(size_t)(r0+8) * Dq + col] = __nv_bfloat162(
                    __float2bfloat16(v1x - __bfloat162float(h1x)),
                    __float2bfloat16(v1y - __bfloat162float(h1y)));
            } else {
                float2 w0, w1;
                w0.x = v0x; w0.y = v0y; w1.x = v1x; w1.y = v1y;
                *(float2*)&C[(size_t)r0 * Dq + col] = w0;
                *(float2*)&C[(size_t)(r0 + 8) * Dq + col] = w1;
            }
        }
    }
}

// ---------------------------------------------------------------------------
// FA2-style HMMA attention, 2-stage cp.async KV pipeline, Q smem-resident.
// Round 7: exp/pack for each k-block interleaved with its PV MMAs so the
// MUFU.EX2 burst overlaps the tensor pipe instead of serializing before it.
// ---------------------------------------------------------------------------
#define AST 72
#define AT_TILE  (64*AST*2)          // 9216 B
#define AT_STAGE (4*AT_TILE)         // 36864 B
#define QBYTES   (128*AST*2)         // 18432 B per Q matrix
#define QLOFF    QBYTES
#define KVOFF    (2*QBYTES)          // 36864
#define AT_SMEM  (KVOFF + 2*AT_STAGE)  // 110592 B

__global__ __launch_bounds__(256, 2)
void attn_mma_kernel(const __nv_bfloat16* __restrict__ Qh, const __nv_bfloat16* __restrict__ Ql,
                     const __nv_bfloat16* __restrict__ Kh, const __nv_bfloat16* __restrict__ Kl,
                     const __nv_bfloat16* __restrict__ Vh, const __nv_bfloat16* __restrict__ Vl,
                     __nv_bfloat16* __restrict__ Ah, __nv_bfloat16* __restrict__ Al)
{
    extern __shared__ char smem[];
    const uint32_t sbase = smem_to_u32(smem);
    const int tid = threadIdx.x, lane = tid & 31, wid = tid >> 5;
    const int bh = blockIdx.y, b = bh >> 4, h = bh & 15;
    const int q0 = blockIdx.x * 128;
    const int g = lane >> 2, t4 = lane & 3;

    // ---- stage Q (scaled by 1/8, exact in bf16); persists whole kernel ----
    {
        __nv_bfloat16* sQh = (__nv_bfloat16*)smem;
        __nv_bfloat16* sQl = sQh + 128*AST;
        const int row = tid >> 1, halfo = (tid & 1) * 32;
        const __nv_bfloat162 sc = __floats2bfloat162_rn(0.125f, 0.125f);
        size_t gq = ((size_t)(b*Sq) + q0 + row) * Dq + h*HDq + halfo;
        #pragma unroll
        for (int u = 0; u < 4; u++) {
            uint4 xh4 = *(const uint4*)(Qh + gq + u*8);
            uint4 xl4 = *(const uint4*)(Ql + gq + u*8);
            __nv_bfloat162* ph = (__nv_bfloat162*)&xh4;
            __nv_bfloat162* pl = (__nv_bfloat162*)&xl4;
            #pragma unroll
            for (int e = 0; e < 4; e++) { ph[e] = __hmul2(ph[e], sc); pl[e] = __hmul2(pl[e], sc); }
            *(uint4*)&sQh[row*AST + halfo + u*8] = xh4;
            *(uint4*)&sQl[row*AST + halfo + u*8] = xl4;
        }
    }

    // KV cp.async issue: each thread 8 x cp16 (2 per matrix)
    const int krow = tid >> 2, kd0 = (tid & 3) * 16;
    const size_t kvrowbase = (size_t)(b*Sq) * Dq + h*HDq + (size_t)krow * Dq + kd0;
    const uint32_t so = (uint32_t)((krow*AST + kd0) * 2);

    auto issue_kv = [&](int tile, int s) {
        size_t gk = kvrowbase + (size_t)tile * 64 * Dq;
        uint32_t sb = sbase + KVOFF + s * AT_STAGE;
        cp16(sb + 0*AT_TILE + so,      Kh + gk);
        cp16(sb + 0*AT_TILE + so + 16, Kh + gk + 8);
        cp16(sb + 1*AT_TILE + so,      Kl + gk);
        cp16(sb + 1*AT_TILE + so + 16, Kl + gk + 8);
        cp16(sb + 2*AT_TILE + so,      Vh + gk);
        cp16(sb + 2*AT_TILE + so + 16, Vh + gk + 8);
        cp16(sb + 3*AT_TILE + so,      Vl + gk);
        cp16(sb + 3*AT_TILE + so + 16, Vl + gk + 8);
    };

    issue_kv(0, 0); cp_commit();
    issue_kv(1, 1); cp_commit();
    __syncthreads();   // Q staged (also orders smem Q writes vs ldsm reads)

    const uint32_t q_rowoff = (uint32_t)(((wid*16 + (lane & 15))*AST + (lane >> 4)*8) * 2);

    float m0 = -1e30f, m1 = -1e30f, l0 = 0.f, l1 = 0.f;
    float o[8][4];
    #pragma unroll
    for (int j = 0; j < 8; j++)
        #pragma unroll
        for (int r = 0; r < 4; r++) o[j][r] = 0.f;

    const uint32_t kb_row = (lane & 7) + ((lane >> 4) & 1) * 8;
    const uint32_t kb_col = ((lane >> 3) & 1) * 8;
    const uint32_t vb_row = (lane & 7) + ((lane >> 3) & 1) * 8;
    const uint32_t vb_col = ((lane >> 4) & 1) * 8;

    for (int tile = 0; tile < Sq/64; tile++) {
        const int s = tile & 1;
        const uint32_t sb = sbase + KVOFF + s * AT_STAGE;
        const uint32_t oKh = sb, oKl = sb + AT_TILE, oVh = sb + 2*AT_TILE, oVl = sb + 3*AT_TILE;

        cp_wait<1>();
        __syncthreads();

        // ---- S = (Q/8) K^T, 3 split terms; Q frags reloaded from smem ----
        float sAcc[8][4];
        #pragma unroll
        for (int j = 0; j < 8; j++)
            #pragma unroll
            for (int r = 0; r < 4; r++) sAcc[j][r] = 0.f;
        #pragma unroll
        for (int kk = 0; kk < 4; kk++) {
            uint32_t qh[4], ql[4];
            ldsm_x4(qh, sbase + q_rowoff + kk*32);
            ldsm_x4(ql, sbase + QLOFF + q_rowoff + kk*32);
            #pragma unroll
            for (int jj = 0; jj < 4; jj++) {
                uint32_t off = (uint32_t)(((jj*16 + kb_row)*AST + kk*16 + kb_col) * 2);
                uint32_t kf[4], lf[4];
                ldsm_x4(kf, oKh + off);
                ldsm_x4(lf, oKl + off);
                mma_bf16(sAcc[2*jj],   qh, &kf[0]);
                mma_bf16(sAcc[2*jj+1], qh, &kf[2]);
                mma_bf16(sAcc[2*jj],   qh, &lf[0]);
                mma_bf16(sAcc[2*jj+1], qh, &lf[2]);
                mma_bf16(sAcc[2*jj],   ql, &kf[0]);
                mma_bf16(sAcc[2*jj+1], ql, &kf[2]);
            }
        }

        // ---- row max + rescale of O (cheap, FMA/ALU pipes) ----
        float mx0 = -1e30f, mx1 = -1e30f;
        #pragma unroll
        for (int j = 0; j < 8; j++) {
            mx0 = fmaxf(mx0, fmaxf(sAcc[j][0], sAcc[j][1]));
            mx1 = fmaxf(mx1, fmaxf(sAcc[j][2], sAcc[j][3]));
        }
        mx0 = fmaxf(mx0, __shfl_xor_sync(0xffffffffu, mx0, 1));
        mx0 = fmaxf(mx0, __shfl_xor_sync(0xffffffffu, mx0, 2));
        mx1 = fmaxf(mx1, __shfl_xor_sync(0xffffffffu, mx1, 1));
        mx1 = fmaxf(mx1, __shfl_xor_sync(0xffffffffu, mx1, 2));
        float mn0 = fmaxf(m0, mx0), mn1 = fmaxf(m1, mx1);
        float c0 = __expf(m0 - mn0), c1 = __expf(m1 - mn1);
        #pragma unroll
        for (int j = 0; j < 8; j++) {
            o[j][0] *= c0; o[j][1] *= c0;
            o[j][2] *= c1; o[j][3] *= c1;
        }
        float sum0 = 0.f, sum1 = 0.f;

        // ---- PV with per-block exp/pack interleave: exps for block kk issue
        //      on MUFU while PV MMAs of block kk-1 run on the tensor pipe ----
        #pragma unroll
        for (int kk = 0; kk < 4; kk++) {
            float* s0 = sAcc[2*kk];
            float* s1 = sAcc[2*kk+1];
            s0[0] = __expf(s0[0] - mn0); sum0 += s0[0];
            s0[1] = __expf(s0[1] - mn0); sum0 += s0[1];
            s0[2] = __expf(s0[2] - mn1); sum1 += s0[2];
            s0[3] = __expf(s0[3] - mn1); sum1 += s0[3];
            s1[0] = __expf(s1[0] - mn0); sum0 += s1[0];
            s1[1] = __expf(s1[1] - mn0); sum0 += s1[1];
            s1[2] = __expf(s1[2] - mn1); sum1 += s1[2];
            s1[3] = __expf(s1[3] - mn1); sum1 += s1[3];

            uint32_t pah[4], pal[4];
            pah[0] = pack_bf16(s0[0], s0[1]);
            pah[1] = pack_bf16(s0[2], s0[3]);
            pah[2] = pack_bf16(s1[0], s1[1]);
            pah[3] = pack_bf16(s1[2], s1[3]);
            __nv_bfloat162 hh;
            hh = *(__nv_bfloat162*)&pah[0];
            pal[0] = pack_bf16(s0[0] - __bfloat162float(hh.x), s0[1] - __bfloat162float(hh.y));
            hh = *(__nv_bfloat162*)&pah[1];
            pal[1] = pack_bf16(s0[2] - __bfloat162float(hh.x), s0[3] - __bfloat162float(hh.y));
            hh = *(__nv_bfloat162*)&pah[2];
            pal[2] = pack_bf16(s1[0] - __bfloat162float(hh.x), s1[1] - __bfloat162float(hh.y));
            hh = *(__nv_bfloat162*)&pah[3];
            pal[3] = pack_bf16(s1[2] - __bfloat162float(hh.x), s1[3] - __bfloat162float(hh.y));

            #pragma unroll
            for (int jj = 0; jj < 4; jj++) {
                uint32_t off = (uint32_t)(((kk*16 + vb_row)*AST + jj*16 + vb_col) * 2);
                uint32_t vh[4], vl[4];
                ldsm_x4_trans(vh, oVh + off);
                ldsm_x4_trans(vl, oVl + off);
                mma_bf16(o[2*jj],   pah, &vh[0]);
                mma_bf16(o[2*jj+1], pah, &vh[2]);
                mma_bf16(o[2*jj],   pah, &vl[0]);
                mma_bf16(o[2*jj+1], pah, &vl[2]);
                mma_bf16(o[2*jj],   pal, &vh[0]);
                mma_bf16(o[2*jj+1], pal, &vh[2]);
            }
        }

        // ---- finish running stats ----
        sum0 += __shfl_xor_sync(0xffffffffu, sum0, 1);
        sum0 += __shfl_xor_sync(0xffffffffu, sum0, 2);
        sum1 += __shfl_xor_sync(0xffffffffu, sum1, 1);
        sum1 += __shfl_xor_sync(0xffffffffu, sum1, 2);
        m0 = mn0; m1 = mn1;
        l0 = l0 * c0 + sum0;
        l1 = l1 * c1 + sum1;

        __syncthreads();
        if (tile + 2 < Sq/64) { issue_kv(tile + 2, s); cp_commit(); }
    }

    // ---- epilogue: normalize, split to bf16 hi/lo ----
    float inv0 = 1.0f / l0, inv1 = 1.0f / l1;
    const int row0 = q0 + wid*16 + g;
    size_t ob0 = ((size_t)(b*Sq) + row0) * Dq + h*HDq;
    size_t ob1 = ob0 + (size_t)8 * Dq;
    #pragma unroll
    for (int j = 0; j < 8; j++) {
        const int c = j*8 + t4*2;
        float f0 = o[j][0] * inv0, f1 = o[j][1] * inv0;
        float f2 = o[j][2] * inv1, f3 = o[j][3] * inv1;
        __nv_bfloat16 h0 = __float2bfloat16(f0), h1 = __float2bfloat16(f1);
        __nv_bfloat16 h2 = __float2bfloat16(f2), h3 = __float2bfloat16(f3);
        *(__nv_bfloat162*)&Ah[ob0 + c] = __nv_bfloat162(h0, h1);
        *(__nv_bfloat162*)&Ah[ob1 + c] = __nv_bfloat162(h2, h3);
        *(__nv_bfloat162*)&Al[ob0 + c] = __nv_bfloat162(
            __float2bfloat16(f0 - __bfloat162float(h0)),
            __float2bfloat16(f1 - __bfloat162float(h1)));
        *(__nv_bfloat162*)&Al[ob1 + c] = __nv_bfloat162(
            __float2bfloat16(f2 - __bfloat162float(h2)),
            __float2bfloat16(f3 - __bfloat162float(h3)));
    }
}

// ---------------------------------------------------------------------------
extern "C" void kernel_launch(void* const* d_in, const int* in_sizes, int n_in,
                              void* d_out, int out_size)
{
    const float* q   = (const float*)d_in[0];
    const float* k   = (const float*)d_in[1];
    const float* v   = (const float*)d_in[2];
    const float* w_q = (const float*)d_in[3];
    const float* b_q = (const float*)d_in[4];
    const float* w_k = (const float*)d_in[5];
    const float* b_k = (const float*)d_in[6];
    const float* w_v = (const float*)d_in[7];
    const float* b_v = (const float*)d_in[8];
    const float* w_fc= (const float*)d_in[9];
    const float* b_fc= (const float*)d_in[10];
    float* out = (float*)d_out;

    __nv_bfloat16 *xh, *xl, *wh, *wl, *Qh, *Ql, *Kh, *Kl, *Vh, *Vl, *Ahp, *Alp;
    cudaGetSymbolAddress((void**)&xh, g_xh);
    cudaGetSymbolAddress((void**)&xl, g_xl);
    cudaGetSymbolAddress((void**)&wh, g_wh);
    cudaGetSymbolAddress((void**)&wl, g_wl);
    cudaGetSymbolAddress((void**)&Qh, g_Qh);
    cudaGetSymbolAddress((void**)&Ql, g_Ql);
    cudaGetSymbolAddress((void**)&Kh, g_Kh);
    cudaGetSymbolAddress((void**)&Kl, g_Kl);
    cudaGetSymbolAddress((void**)&Vh, g_Vh);
    cudaGetSymbolAddress((void**)&Vl, g_Vl);
    cudaGetSymbolAddress((void**)&Ahp, g_Ah);
    cudaGetSymbolAddress((void**)&Alp, g_Al);

    cudaFuncSetAttribute(gemm_mma_kernel<true>,
                         cudaFuncAttributeMaxDynamicSharedMemorySize, GSMEM);
    cudaFuncSetAttribute(gemm_mma_kernel<false>,
                         cudaFuncAttributeMaxDynamicSharedMemorySize, GSMEM);
    cudaFuncSetAttribute(attn_mma_kernel,
                         cudaFuncAttributeMaxDynamicSharedMemorySize, AT_SMEM);

    const int actN4 = BSq*Dq/4;
    const int wN4   = DD/4;
    dim3 sblk(256);

    // all 4 weight splits, one launch
    split_w_kernel<<<dim3((wN4 + 255)/256, 4), sblk>>>(
        (const float4*)w_q, (const float4*)w_k, (const float4*)w_v, (const float4*)w_fc,
        (__nv_bfloat162*)wh, (__nv_bfloat162*)wl, wN4);

    // all 3 activation splits, one launch
    split_act_kernel<<<dim3((actN4 + 255)/256, 3), sblk>>>(
        (const float4*)q, (const float4*)k, (const float4*)v,
        (__nv_bfloat162*)xh, (__nv_bfloat162*)xl, actN4);

    // Q/K/V projections, one launch (grid.z selects matrix)
    gemm_mma_kernel<true><<<dim3(Dq/128, BSq/128, 3), 256, GSMEM>>>(
        xh, xl, wh, wl, b_q, b_k, b_v, nullptr,
        Qh, Ql, Kh, Kl, Vh, Vl);

    // attention (tensor cores, split precision, pipelined KV, occ=2)
    attn_mma_kernel<<<dim3(Sq/128, Bq*Hq), 256, AT_SMEM>>>(Qh, Ql, Kh, Kl, Vh, Vl, Ahp, Alp);

    // output projection (fp32 out)
    gemm_mma_kernel<false><<<dim3(Dq/128, BSq/128, 1), 256, GSMEM>>>(
        Ahp, Alp, wh + 3*DD, wl + 3*DD, b_fc, b_fc, b_fc, out,
        nullptr, nullptr, nullptr, nullptr, nullptr, nullptr);
}

// round 8
// speedup vs baseline: 4.7531x; 1.3697x over previous
#include <cuda_runtime.h>
#include <cuda_bf16.h>
#include <cuda_fp16.h>
#include <cstdint>

#define Bq 4
#define Sq 2048
#define Dq 1024
#define Hq 16
#define HDq 64
#define BSq (Bq*Sq)   // 8192
#define DD  (Dq*Dq)

// ---------------- scratch (__device__ globals; no allocs allowed) ----------
__device__ __nv_bfloat16 g_xh[3*BSq*Dq];
__device__ __nv_bfloat16 g_xl[3*BSq*Dq];
__device__ __nv_bfloat16 g_wh[4*DD];
__device__ __nv_bfloat16 g_wl[4*DD];
__device__ __half        g_Q16[BSq*Dq];
__device__ __half        g_K16[BSq*Dq];
__device__ __half        g_V16[BSq*Dq];
__device__ __nv_bfloat16 g_Ah[BSq*Dq];
__device__ __nv_bfloat16 g_Al[BSq*Dq];

__device__ __forceinline__ uint32_t smem_to_u32(const void* p) {
    uint32_t a;
    asm("{ .reg .u64 t; cvta.to.shared.u64 t, %1; cvt.u32.u64 %0, t; }"
        : "=r"(a) : "l"(p));
    return a;
}
__device__ __forceinline__ void cp16(uint32_t dst, const void* src) {
    asm volatile("cp.async.cg.shared.global [%0], [%1], 16;"
                 :: "r"(dst), "l"(src) : "memory");
}
__device__ __forceinline__ void cp_commit() {
    asm volatile("cp.async.commit_group;" ::: "memory");
}
template <int N>
__device__ __forceinline__ void cp_wait() {
    asm volatile("cp.async.wait_group %0;" :: "n"(N) : "memory");
}
__device__ __forceinline__ void ldsm_x4(uint32_t* r, uint32_t addr) {
    asm volatile("ldmatrix.sync.aligned.m8n8.x4.shared.b16 {%0,%1,%2,%3}, [%4];"
                 : "=r"(r[0]), "=r"(r[1]), "=r"(r[2]), "=r"(r[3]) : "r"(addr));
}
__device__ __forceinline__ void ldsm_x4_trans(uint32_t* r, uint32_t addr) {
    asm volatile("ldmatrix.sync.aligned.m8n8.x4.trans.shared.b16 {%0,%1,%2,%3}, [%4];"
                 : "=r"(r[0]), "=r"(r[1]), "=r"(r[2]), "=r"(r[3]) : "r"(addr));
}
__device__ __forceinline__ void mma_bf16(float* d, const uint32_t* a, const uint32_t* b) {
    asm volatile(
        "mma.sync.aligned.m16n8k16.row.col.f32.bf16.bf16.f32 "
        "{%0,%1,%2,%3}, {%4,%5,%6,%7}, {%8,%9}, {%0,%1,%2,%3};"
        : "+f"(d[0]), "+f"(d[1]), "+f"(d[2]), "+f"(d[3])
        : "r"(a[0]), "r"(a[1]), "r"(a[2]), "r"(a[3]), "r"(b[0]), "r"(b[1]));
}
__device__ __forceinline__ void mma_f16(float* d, const uint32_t* a, const uint32_t* b) {
    asm volatile(
        "mma.sync.aligned.m16n8k16.row.col.f32.f16.f16.f32 "
        "{%0,%1,%2,%3}, {%4,%5,%6,%7}, {%8,%9}, {%0,%1,%2,%3};"
        : "+f"(d[0]), "+f"(d[1]), "+f"(d[2]), "+f"(d[3])
        : "r"(a[0]), "r"(a[1]), "r"(a[2]), "r"(a[3]), "r"(b[0]), "r"(b[1]));
}
__device__ __forceinline__ uint32_t pack_h16(float x, float y) {
    __half2 v = __floats2half2_rn(x, y);
    return *(uint32_t*)&v;
}

// ---------------------------------------------------------------------------
// Batched fp32 -> (bf16 hi, bf16 lo) splits
// ---------------------------------------------------------------------------
__device__ __forceinline__ void split_body(const float4* __restrict__ x,
                                           __nv_bfloat162* __restrict__ hi,
                                           __nv_bfloat162* __restrict__ lo, int n4)
{
    int i = blockIdx.x * blockDim.x + threadIdx.x;
    if (i >= n4) return;
    float4 v = x[i];
    __nv_bfloat16 h0 = __float2bfloat16(v.x);
    __nv_bfloat16 h1 = __float2bfloat16(v.y);
    __nv_bfloat16 h2 = __float2bfloat16(v.z);
    __nv_bfloat16 h3 = __float2bfloat16(v.w);
    hi[i*2 + 0] = __nv_bfloat162(h0, h1);
    hi[i*2 + 1] = __nv_bfloat162(h2, h3);
    lo[i*2 + 0] = __nv_bfloat162(
        __float2bfloat16(v.x - __bfloat162float(h0)),
        __float2bfloat16(v.y - __bfloat162float(h1)));
    lo[i*2 + 1] = __nv_bfloat162(
        __float2bfloat16(v.z - __bfloat162float(h2)),
        __float2bfloat16(v.w - __bfloat162float(h3)));
}

__global__ void split_act_kernel(const float4* __restrict__ q, const float4* __restrict__ k,
                                 const float4* __restrict__ v,
                                 __nv_bfloat162* __restrict__ hi,
                                 __nv_bfloat162* __restrict__ lo, int n4)
{
    const int z = blockIdx.y;
    const float4* x = (z == 0) ? q : (z == 1) ? k : v;
    split_body(x, hi + (size_t)z * n4 * 2, lo + (size_t)z * n4 * 2, n4);
}

__global__ void split_w_kernel(const float4* __restrict__ w0, const float4* __restrict__ w1,
                               const float4* __restrict__ w2, const float4* __restrict__ w3,
                               __nv_bfloat162* __restrict__ hi,
                               __nv_bfloat162* __restrict__ lo, int n4)
{
    const int z = blockIdx.y;
    const float4* x = (z == 0) ? w0 : (z == 1) ? w1 : (z == 2) ? w2 : w3;
    split_body(x, hi + (size_t)z * n4 * 2, lo + (size_t)z * n4 * 2, n4);
}

// ---------------------------------------------------------------------------
// HMMA split-GEMM, batched over blockIdx.z.
// MODE 0: fp32 out.  MODE 2: fp16 out (Q/K/V for attention).
// CTA 128x128, 8 warps (warp tile 64x32), K-chunk 32, 2-stage cp.async.
// ---------------------------------------------------------------------------
#define GSTRIDE 40
#define GMAT    (128*GSTRIDE*2)
#define GSTAGE  (4*GMAT)
#define GSMEM   (2*GSTAGE)
#define NCHUNK  (Dq/32)

template<int MODE>
__global__ __launch_bounds__(256, 2)
void gemm_mma_kernel(const __nv_bfloat16* __restrict__ Ahb,
                     const __nv_bfloat16* __restrict__ Alb,
                     const __nv_bfloat16* __restrict__ Whb,
                     const __nv_bfloat16* __restrict__ Wlb,
                     const float* __restrict__ bias0, const float* __restrict__ bias1,
                     const float* __restrict__ bias2,
                     float* __restrict__ C,
                     __half* __restrict__ H0, __half* __restrict__ H1,
                     __half* __restrict__ H2)
{
    extern __shared__ char smem[];
    const uint32_t smem_base = smem_to_u32(smem);
    const int tid  = threadIdx.x;
    const int lane = tid & 31;
    const int wid  = tid >> 5;
    const int z  = blockIdx.z;
    const int m0 = blockIdx.y * 128;
    const int n0 = blockIdx.x * 128;
    const int wm0 = (wid & 1) * 64;
    const int wn0 = (wid >> 1) * 32;

    const float* bias = (z == 0) ? bias0 : (z == 1) ? bias1 : bias2;
    __half* H = (z == 0) ? H0 : (z == 1) ? H1 : H2;

    const int id0 = tid, id1 = tid + 256;
    const int row0 = id0 >> 2, kq0 = (id0 & 3) * 8;
    const int row1 = id1 >> 2, kq1 = (id1 & 3) * 8;

    const __nv_bfloat16* gAh = Ahb + (size_t)z * BSq * Dq + (size_t)m0 * Dq;
    const __nv_bfloat16* gAl = Alb + (size_t)z * BSq * Dq + (size_t)m0 * Dq;
    const __nv_bfloat16* gWh = Whb + (size_t)z * DD + (size_t)n0 * Dq;
    const __nv_bfloat16* gWl = Wlb + (size_t)z * DD + (size_t)n0 * Dq;

    float acc[4][4][4];
    #pragma unroll
    for (int i = 0; i < 4; i++)
        #pragma unroll
        for (int j = 0; j < 4; j++)
            #pragma unroll
            for (int r = 0; r < 4; r++) acc[i][j][r] = 0.f;

    auto issue = [&](int c, int s) {
        const int k0 = c * 32;
        uint32_t sb = smem_base + s * GSTAGE;
        uint32_t d0 = (uint32_t)(row0 * (GSTRIDE*2) + kq0 * 2);
        uint32_t d1 = (uint32_t)(row1 * (GSTRIDE*2) + kq1 * 2);
        size_t s0 = (size_t)row0 * Dq + k0 + kq0;
        size_t s1 = (size_t)row1 * Dq + k0 + kq1;
        cp16(sb + 0*GMAT + d0, gAh + s0);
        cp16(sb + 0*GMAT + d1, gAh + s1);
        cp16(sb + 1*GMAT + d0, gAl + s0);
        cp16(sb + 1*GMAT + d1, gAl + s1);
        cp16(sb + 2*GMAT + d0, gWh + s0);
        cp16(sb + 2*GMAT + d1, gWh + s1);
        cp16(sb + 3*GMAT + d0, gWl + s0);
        cp16(sb + 3*GMAT + d1, gWl + s1);
    };

    issue(0, 0);
    cp_commit();

    const int a_r = wm0 + (lane & 15);
    const int a_c = (lane >> 4) * 8;
    const int b_r = wn0 + (lane & 7) + ((lane >> 4) << 3);
    const int b_c = ((lane >> 3) & 1) * 8;

    for (int c = 0; c < NCHUNK; c++) {
        const int s = c & 1;
        if (c + 1 < NCHUNK) { issue(c + 1, s ^ 1); cp_commit(); }
        if (c + 1 < NCHUNK) cp_wait<1>(); else cp_wait<0>();
        __syncthreads();

        const uint32_t sb = smem_base + s * GSTAGE;
        const uint32_t aH = sb + 0*GMAT, aL = sb + 1*GMAT;
        const uint32_t wH = sb + 2*GMAT, wL = sb + 3*GMAT;

        #pragma unroll
        for (int kk = 0; kk < 2; kk++) {
            const int k16 = kk * 16;
            uint32_t bh[2][4], bl[2][4];
            #pragma unroll
            for (int jj = 0; jj < 2; jj++) {
                uint32_t off = (uint32_t)((b_r + jj*16) * (GSTRIDE*2) + (k16 + b_c) * 2);
                ldsm_x4(bh[jj], wH + off);
                ldsm_x4(bl[jj], wL + off);
            }
            #pragma unroll
            for (int i = 0; i < 4; i++) {
                uint32_t ah[4], al[4];
                uint32_t off = (uint32_t)((a_r + i*16) * (GSTRIDE*2) + (k16 + a_c) * 2);
                ldsm_x4(ah, aH + off);
                ldsm_x4(al, aL + off);
                #pragma unroll
                for (int j = 0; j < 4; j++) {
                    const uint32_t* bhp = &bh[j >> 1][(j & 1) * 2];
                    const uint32_t* blp = &bl[j >> 1][(j & 1) * 2];
                    mma_bf16(acc[i][j], ah, bhp);
                    mma_bf16(acc[i][j], ah, blp);
                    mma_bf16(acc[i][j], al, bhp);
                }
            }
        }
        __syncthreads();
    }

    // epilogue
    const int g = lane >> 2, t = lane & 3;
    #pragma unroll
    for (int j = 0; j < 4; j++) {
        const int col = n0 + wn0 + j*8 + t*2;
        const float bx = __ldg(&bias[col]);
        const float by = __ldg(&bias[col + 1]);
        #pragma unroll
        for (int i = 0; i < 4; i++) {
            const int r0 = m0 + wm0 + i*16 + g;
            float v0x = acc[i][j][0] + bx, v0y = acc[i][j][1] + by;
            float v1x = acc[i][j][2] + bx, v1y = acc[i][j][3] + by;
            if (MODE == 2) {
                *(__half2*)&H[(size_t)r0 * Dq + col] = __floats2half2_rn(v0x, v0y);
                *(__half2*)&H[(size_t)(r0+8) * Dq + col] = __floats2half2_rn(v1x, v1y);
            } else {
                float2 w0, w1;
                w0.x = v0x; w0.y = v0y; w1.x = v1x; w1.y = v1y;
                *(float2*)&C[(size_t)r0 * Dq + col] = w0;
                *(float2*)&C[(size_t)(r0 + 8) * Dq + col] = w1;
            }
        }
    }
}

// ---------------------------------------------------------------------------
// FA2-style HMMA attention, fp16 single precision internals, fp32 accum.
// 2-stage cp.async KV pipeline, Q fragments register-resident.
// smem: [0, 18432) Q fp16; then 2 stages x {K,V} 64x64 fp16 (AST-padded).
// ---------------------------------------------------------------------------
#define AST 72
#define AT_TILE  (64*AST*2)          // 9216 B per matrix
#define AT_STAGE (2*AT_TILE)         // 18432 B per stage (K+V)
#define QBYTES   (128*AST*2)         // 18432 B
#define KVOFF    QBYTES
#define AT_SMEM  (KVOFF + 2*AT_STAGE)  // 55296 B

__global__ __launch_bounds__(256, 2)
void attn_mma_kernel(const __half* __restrict__ Q16, const __half* __restrict__ K16,
                     const __half* __restrict__ V16,
                     __nv_bfloat16* __restrict__ Ah, __nv_bfloat16* __restrict__ Al)
{
    extern __shared__ char smem[];
    const uint32_t sbase = smem_to_u32(smem);
    const int tid = threadIdx.x, lane = tid & 31, wid = tid >> 5;
    const int bh = blockIdx.y, b = bh >> 4, h = bh & 15;
    const int q0 = blockIdx.x * 128;
    const int g = lane >> 2, t4 = lane & 3;

    // ---- stage Q (scaled by 1/8, exact in fp16) ----
    {
        __half* sQ = (__half*)smem;
        const int row = tid >> 1, halfo = (tid & 1) * 32;
        const __half2 sc = __floats2half2_rn(0.125f, 0.125f);
        size_t gq = ((size_t)(b*Sq) + q0 + row) * Dq + h*HDq + halfo;
        #pragma unroll
        for (int u = 0; u < 4; u++) {
            uint4 x4 = *(const uint4*)(Q16 + gq + u*8);
            __half2* p = (__half2*)&x4;
            #pragma unroll
            for (int e = 0; e < 4; e++) p[e] = __hmul2(p[e], sc);
            *(uint4*)&sQ[row*AST + halfo + u*8] = x4;
        }
    }

    // KV cp.async issue: each thread 4 x cp16 (2 per matrix)
    const int krow = tid >> 2, kd0 = (tid & 3) * 16;
    const size_t kvrowbase = (size_t)(b*Sq) * Dq + h*HDq + (size_t)krow * Dq + kd0;
    const uint32_t so = (uint32_t)((krow*AST + kd0) * 2);

    auto issue_kv = [&](int tile, int s) {
        size_t gk = kvrowbase + (size_t)tile * 64 * Dq;
        uint32_t sb = sbase + KVOFF + s * AT_STAGE;
        cp16(sb + 0*AT_TILE + so,      K16 + gk);
        cp16(sb + 0*AT_TILE + so + 16, K16 + gk + 8);
        cp16(sb + 1*AT_TILE + so,      V16 + gk);
        cp16(sb + 1*AT_TILE + so + 16, V16 + gk + 8);
    };

    issue_kv(0, 0); cp_commit();
    issue_kv(1, 1); cp_commit();
    __syncthreads();   // Q staged

    // Q fragments -> registers (16 regs)
    uint32_t qf[4][4];
    {
        uint32_t rowoff = (uint32_t)(((wid*16 + (lane & 15))*AST + (lane >> 4)*8) * 2);
        #pragma unroll
        for (int kk = 0; kk < 4; kk++)
            ldsm_x4(qf[kk], sbase + rowoff + kk*32);
    }

    float m0 = -1e30f, m1 = -1e30f, l0 = 0.f, l1 = 0.f;
    float o[8][4];
    #pragma unroll
    for (int j = 0; j < 8; j++)
        #pragma unroll
        for (int r = 0; r < 4; r++) o[j][r] = 0.f;

    const uint32_t kb_row = (lane & 7) + ((lane >> 4) & 1) * 8;
    const uint32_t kb_col = ((lane >> 3) & 1) * 8;
    const uint32_t vb_row = (lane & 7) + ((lane >> 3) & 1) * 8;
    const uint32_t vb_col = ((lane >> 4) & 1) * 8;

    for (int tile = 0; tile < Sq/64; tile++) {
        const int s = tile & 1;
        const uint32_t sb = sbase + KVOFF + s * AT_STAGE;
        const uint32_t oK = sb, oV = sb + AT_TILE;

        cp_wait<1>();
        __syncthreads();

        // ---- S = (Q/8) K^T ----
        float sAcc[8][4];
        #pragma unroll
        for (int j = 0; j < 8; j++)
            #pragma unroll
            for (int r = 0; r < 4; r++) sAcc[j][r] = 0.f;
        #pragma unroll
        for (int kk = 0; kk < 4; kk++) {
            #pragma unroll
            for (int jj = 0; jj < 4; jj++) {
                uint32_t off = (uint32_t)(((jj*16 + kb_row)*AST + kk*16 + kb_col) * 2);
                uint32_t kf[4];
                ldsm_x4(kf, oK + off);
                mma_f16(sAcc[2*jj],   qf[kk], &kf[0]);
                mma_f16(sAcc[2*jj+1], qf[kk], &kf[2]);
            }
        }

        // ---- online softmax ----
        float mx0 = -1e30f, mx1 = -1e30f;
        #pragma unroll
        for (int j = 0; j < 8; j++) {
            mx0 = fmaxf(mx0, fmaxf(sAcc[j][0], sAcc[j][1]));
            mx1 = fmaxf(mx1, fmaxf(sAcc[j][2], sAcc[j][3]));
        }
        mx0 = fmaxf(mx0, __shfl_xor_sync(0xffffffffu, mx0, 1));
        mx0 = fmaxf(mx0, __shfl_xor_sync(0xffffffffu, mx0, 2));
        mx1 = fmaxf(mx1, __shfl_xor_sync(0xffffffffu, mx1, 1));
        mx1 = fmaxf(mx1, __shfl_xor_sync(0xffffffffu, mx1, 2));
        float mn0 = fmaxf(m0, mx0), mn1 = fmaxf(m1, mx1);
        float c0 = __expf(m0 - mn0), c1 = __expf(m1 - mn1);
        #pragma unroll
        for (int j = 0; j < 8; j++) {
            o[j][0] *= c0; o[j][1] *= c0;
            o[j][2] *= c1; o[j][3] *= c1;
        }
        float sum0 = 0.f, sum1 = 0.f;

        // ---- exp + pack + PV (interleaved per key-block) ----
        #pragma unroll
        for (int kk = 0; kk < 4; kk++) {
            float* s0 = sAcc[2*kk];
            float* s1 = sAcc[2*kk+1];
            s0[0] = __expf(s0[0] - mn0); sum0 += s0[0];
            s0[1] = __expf(s0[1] - mn0); sum0 += s0[1];
            s0[2] = __expf(s0[2] - mn1); sum1 += s0[2];
            s0[3] = __expf(s0[3] - mn1); sum1 += s0[3];
            s1[0] = __expf(s1[0] - mn0); sum0 += s1[0];
            s1[1] = __expf(s1[1] - mn0); sum0 += s1[1];
            s1[2] = __expf(s1[2] - mn1); sum1 += s1[2];
            s1[3] = __expf(s1[3] - mn1); sum1 += s1[3];

            uint32_t pf[4];
            pf[0] = pack_h16(s0[0], s0[1]);
            pf[1] = pack_h16(s0[2], s0[3]);
            pf[2] = pack_h16(s1[0], s1[1]);
            pf[3] = pack_h16(s1[2], s1[3]);

            #pragma unroll
            for (int jj = 0; jj < 4; jj++) {
                uint32_t off = (uint32_t)(((kk*16 + vb_row)*AST + jj*16 + vb_col) * 2);
                uint32_t vf[4];
                ldsm_x4_trans(vf, oV + off);
                mma_f16(o[2*jj],   pf, &vf[0]);
                mma_f16(o[2*jj+1], pf, &vf[2]);
            }
        }

        sum0 += __shfl_xor_sync(0xffffffffu, sum0, 1);
        sum0 += __shfl_xor_sync(0xffffffffu, sum0, 2);
        sum1 += __shfl_xor_sync(0xffffffffu, sum1, 1);
        sum1 += __shfl_xor_sync(0xffffffffu, sum1, 2);
        m0 = mn0; m1 = mn1;
        l0 = l0 * c0 + sum0;
        l1 = l1 * c1 + sum1;

        __syncthreads();
        if (tile + 2 < Sq/64) { issue_kv(tile + 2, s); cp_commit(); }
    }

    // ---- epilogue: normalize, split to bf16 hi/lo for fc GEMM ----
    float inv0 = 1.0f / l0, inv1 = 1.0f / l1;
    const int row0 = q0 + wid*16 + g;
    size_t ob0 = ((size_t)(b*Sq) + row0) * Dq + h*HDq;
    size_t ob1 = ob0 + (size_t)8 * Dq;
    #pragma unroll
    for (int j = 0; j < 8; j++) {
        const int c = j*8 + t4*2;
        float f0 = o[j][0] * inv0, f1 = o[j][1] * inv0;
        float f2 = o[j][2] * inv1, f3 = o[j][3] * inv1;
        __nv_bfloat16 h0 = __float2bfloat16(f0), h1 = __float2bfloat16(f1);
        __nv_bfloat16 h2 = __float2bfloat16(f2), h3 = __float2bfloat16(f3);
        *(__nv_bfloat162*)&Ah[ob0 + c] = __nv_bfloat162(h0, h1);
        *(__nv_bfloat162*)&Ah[ob1 + c] = __nv_bfloat162(h2, h3);
        *(__nv_bfloat162*)&Al[ob0 + c] = __nv_bfloat162(
            __float2bfloat16(f0 - __bfloat162float(h0)),
            __float2bfloat16(f1 - __bfloat162float(h1)));
        *(__nv_bfloat162*)&Al[ob1 + c] = __nv_bfloat162(
            __float2bfloat16(f2 - __bfloat162float(h2)),
            __float2bfloat16(f3 - __bfloat162float(h3)));
    }
}

// ---------------------------------------------------------------------------
extern "C" void kernel_launch(void* const* d_in, const int* in_sizes, int n_in,
                              void* d_out, int out_size)
{
    const float* q   = (const float*)d_in[0];
    const float* k   = (const float*)d_in[1];
    const float* v   = (const float*)d_in[2];
    const float* w_q = (const float*)d_in[3];
    const float* b_q = (const float*)d_in[4];
    const float* w_k = (const float*)d_in[5];
    const float* b_k = (const float*)d_in[6];
    const float* w_v = (const float*)d_in[7];
    const float* b_v = (const float*)d_in[8];
    const float* w_fc= (const float*)d_in[9];
    const float* b_fc= (const float*)d_in[10];
    float* out = (float*)d_out;

    __nv_bfloat16 *xh, *xl, *wh, *wl, *Ahp, *Alp;
    __half *Q16, *K16, *V16;
    cudaGetSymbolAddress((void**)&xh, g_xh);
    cudaGetSymbolAddress((void**)&xl, g_xl);
    cudaGetSymbolAddress((void**)&wh, g_wh);
    cudaGetSymbolAddress((void**)&wl, g_wl);
    cudaGetSymbolAddress((void**)&Q16, g_Q16);
    cudaGetSymbolAddress((void**)&K16, g_K16);
    cudaGetSymbolAddress((void**)&V16, g_V16);
    cudaGetSymbolAddress((void**)&Ahp, g_Ah);
    cudaGetSymbolAddress((void**)&Alp, g_Al);

    cudaFuncSetAttribute(gemm_mma_kernel<0>,
                         cudaFuncAttributeMaxDynamicSharedMemorySize, GSMEM);
    cudaFuncSetAttribute(gemm_mma_kernel<2>,
                         cudaFuncAttributeMaxDynamicSharedMemorySize, GSMEM);
    cudaFuncSetAttribute(attn_mma_kernel,
                         cudaFuncAttributeMaxDynamicSharedMemorySize, AT_SMEM);

    const int actN4 = BSq*Dq/4;
    const int wN4   = DD/4;
    dim3 sblk(256);

    // all 4 weight splits, one launch
    split_w_kernel<<<dim3((wN4 + 255)/256, 4), sblk>>>(
        (const float4*)w_q, (const float4*)w_k, (const float4*)w_v, (const float4*)w_fc,
        (__nv_bfloat162*)wh, (__nv_bfloat162*)wl, wN4);

    // all 3 activation splits, one launch
    split_act_kernel<<<dim3((actN4 + 255)/256, 3), sblk>>>(
        (const float4*)q, (const float4*)k, (const float4*)v,
        (__nv_bfloat162*)xh, (__nv_bfloat162*)xl, actN4);

    // Q/K/V projections, one launch -> fp16 outputs
    gemm_mma_kernel<2><<<dim3(Dq/128, BSq/128, 3), 256, GSMEM>>>(
        xh, xl, wh, wl, b_q, b_k, b_v, nullptr, Q16, K16, V16);

    // attention (fp16 internals, fp32 accum; writes bf16 hi/lo)
    attn_mma_kernel<<<dim3(Sq/128, Bq*Hq), 256, AT_SMEM>>>(Q16, K16, V16, Ahp, Alp);

    // output projection (split-bf16 inputs, fp32 out)
    gemm_mma_kernel<0><<<dim3(Dq/128, BSq/128, 1), 256, GSMEM>>>(
        Ahp, Alp, wh + 3*DD, wl + 3*DD, b_fc, b_fc, b_fc, out,
        nullptr, nullptr, nullptr);
}

// round 10
// speedup vs baseline: 6.3815x; 1.3426x over previous
#include <cuda_runtime.h>
#include <cuda_bf16.h>
#include <cuda_fp16.h>
#include <cstdint>

#define Bq 4
#define Sq 2048
#define Dq 1024
#define Hq 16
#define HDq 64
#define BSq (Bq*Sq)   // 8192
#define DD  (Dq*Dq)

// ---------------- scratch (__device__ globals; no allocs allowed) ----------
__device__ __half g_x16[3*BSq*Dq];    // activation fp16 (q,k,v)
__device__ __half g_w16h[3*DD];       // QKV weights hi
__device__ __half g_w16l[3*DD];       // QKV weights lo
__device__ __half g_wfc16[DD];        // fc weight single fp16
__device__ __half g_Q16[BSq*Dq];
__device__ __half g_K16[BSq*Dq];
__device__ __half g_V16[BSq*Dq];
__device__ __half g_A16[BSq*Dq];      // attention output fp16

__device__ __forceinline__ uint32_t smem_to_u32(const void* p) {
    uint32_t a;
    asm("{ .reg .u64 t; cvta.to.shared.u64 t, %1; cvt.u32.u64 %0, t; }"
        : "=r"(a) : "l"(p));
    return a;
}
__device__ __forceinline__ void cp16(uint32_t dst, const void* src) {
    asm volatile("cp.async.cg.shared.global [%0], [%1], 16;"
                 :: "r"(dst), "l"(src) : "memory");
}
__device__ __forceinline__ void cp_commit() {
    asm volatile("cp.async.commit_group;" ::: "memory");
}
template <int N>
__device__ __forceinline__ void cp_wait() {
    asm volatile("cp.async.wait_group %0;" :: "n"(N) : "memory");
}
__device__ __forceinline__ void ldsm_x4(uint32_t* r, uint32_t addr) {
    asm volatile("ldmatrix.sync.aligned.m8n8.x4.shared.b16 {%0,%1,%2,%3}, [%4];"
                 : "=r"(r[0]), "=r"(r[1]), "=r"(r[2]), "=r"(r[3]) : "r"(addr));
}
__device__ __forceinline__ void ldsm_x4_trans(uint32_t* r, uint32_t addr) {
    asm volatile("ldmatrix.sync.aligned.m8n8.x4.trans.shared.b16 {%0,%1,%2,%3}, [%4];"
                 : "=r"(r[0]), "=r"(r[1]), "=r"(r[2]), "=r"(r[3]) : "r"(addr));
}
__device__ __forceinline__ void mma_f16(float* d, const uint32_t* a, const uint32_t* b) {
    asm volatile(
        "mma.sync.aligned.m16n8k16.row.col.f32.f16.f16.f32 "
        "{%0,%1,%2,%3}, {%4,%5,%6,%7}, {%8,%9}, {%0,%1,%2,%3};"
        : "+f"(d[0]), "+f"(d[1]), "+f"(d[2]), "+f"(d[3])
        : "r"(a[0]), "r"(a[1]), "r"(a[2]), "r"(a[3]), "r"(b[0]), "r"(b[1]));
}
__device__ __forceinline__ uint32_t pack_h16(float x, float y) {
    __half2 v = __floats2half2_rn(x, y);
    return *(uint32_t*)&v;
}

// ---------------------------------------------------------------------------
// Splits / converts
// ---------------------------------------------------------------------------
__global__ void split_act16(const float4* __restrict__ q, const float4* __restrict__ k,
                            const float4* __restrict__ v,
                            __half2* __restrict__ x16, int n4)
{
    const int z = blockIdx.y;
    const float4* x = (z == 0) ? q : (z == 1) ? k : v;
    int i = blockIdx.x * blockDim.x + threadIdx.x;
    if (i >= n4) return;
    float4 w = x[i];
    __half2* o = x16 + (size_t)z * n4 * 2;
    o[i*2 + 0] = __floats2half2_rn(w.x, w.y);
    o[i*2 + 1] = __floats2half2_rn(w.z, w.w);
}

__global__ void split_w16(const float4* __restrict__ w0, const float4* __restrict__ w1,
                          const float4* __restrict__ w2, const float4* __restrict__ w3,
                          __half2* __restrict__ h16, __half2* __restrict__ l16,
                          __half2* __restrict__ fc16, int n4)
{
    const int z = blockIdx.y;
    const float4* x = (z == 0) ? w0 : (z == 1) ? w1 : (z == 2) ? w2 : w3;
    int i = blockIdx.x * blockDim.x + threadIdx.x;
    if (i >= n4) return;
    float4 v = x[i];
    __half h0 = __float2half_rn(v.x), h1 = __float2half_rn(v.y);
    __half h2 = __float2half_rn(v.z), h3 = __float2half_rn(v.w);
    if (z < 3) {
        __half2* hp = h16 + (size_t)z * n4 * 2;
        __half2* lp = l16 + (size_t)z * n4 * 2;
        hp[i*2 + 0] = __half2(h0, h1);
        hp[i*2 + 1] = __half2(h2, h3);
        lp[i*2 + 0] = __half2(__float2half_rn(v.x - __half2float(h0)),
                              __float2half_rn(v.y - __half2float(h1)));
        lp[i*2 + 1] = __half2(__float2half_rn(v.z - __half2float(h2)),
                              __float2half_rn(v.w - __half2float(h3)));
    } else {
        fc16[i*2 + 0] = __half2(h0, h1);
        fc16[i*2 + 1] = __half2(h2, h3);
    }
}

// ---------------------------------------------------------------------------
// fp16 HMMA GEMM. A single fp16; NW=2 -> W hi/lo (2 terms), NW=1 -> W single.
// F32OUT: fp32 C (+bias), else fp16 H (+bias).
// CTA 128x128, 8 warps (64x32 warp tile), K-chunk 32, 2-stage cp.async.
// ---------------------------------------------------------------------------
#define GSTRIDE 40
#define GMAT    (128*GSTRIDE*2)     // 10240 B
#define NCHUNK  (Dq/32)

template<int NW, bool F32OUT>
__global__ __launch_bounds__(256, 2)
void gemm16_kernel(const __half* __restrict__ Ab,
                   const __half* __restrict__ W0b,
                   const __half* __restrict__ W1b,
                   const float* __restrict__ bias0, const float* __restrict__ bias1,
                   const float* __restrict__ bias2,
                   float* __restrict__ C,
                   __half* __restrict__ H0, __half* __restrict__ H1,
                   __half* __restrict__ H2)
{
    constexpr int NMAT = NW + 1;
    constexpr int STG  = NMAT * GMAT;
    extern __shared__ char smem[];
    const uint32_t smem_base = smem_to_u32(smem);
    const int tid  = threadIdx.x;
    const int lane = tid & 31;
    const int wid  = tid >> 5;
    const int z  = blockIdx.z;
    const int m0 = blockIdx.y * 128;
    const int n0 = blockIdx.x * 128;
    const int wm0 = (wid & 1) * 64;
    const int wn0 = (wid >> 1) * 32;

    const float* bias = (z == 0) ? bias0 : (z == 1) ? bias1 : bias2;
    __half* H = (z == 0) ? H0 : (z == 1) ? H1 : H2;

    const int id0 = tid, id1 = tid + 256;
    const int row0 = id0 >> 2, kq0 = (id0 & 3) * 8;
    const int row1 = id1 >> 2, kq1 = (id1 & 3) * 8;

    const __half* gA  = Ab  + (size_t)z * BSq * Dq + (size_t)m0 * Dq;
    const __half* gW0 = W0b + (size_t)z * DD + (size_t)n0 * Dq;
    const __half* gW1 = (NW == 2) ? (W1b + (size_t)z * DD + (size_t)n0 * Dq) : nullptr;

    float acc[4][4][4];
    #pragma unroll
    for (int i = 0; i < 4; i++)
        #pragma unroll
        for (int j = 0; j < 4; j++)
            #pragma unroll
            for (int r = 0; r < 4; r++) acc[i][j][r] = 0.f;

    auto issue = [&](int c, int s) {
        const int k0 = c * 32;
        uint32_t sb = smem_base + s * STG;
        uint32_t d0 = (uint32_t)(row0 * (GSTRIDE*2) + kq0 * 2);
        uint32_t d1 = (uint32_t)(row1 * (GSTRIDE*2) + kq1 * 2);
        size_t s0 = (size_t)row0 * Dq + k0 + kq0;
        size_t s1 = (size_t)row1 * Dq + k0 + kq1;
        cp16(sb + 0*GMAT + d0, gA + s0);
        cp16(sb + 0*GMAT + d1, gA + s1);
        cp16(sb + 1*GMAT + d0, gW0 + s0);
        cp16(sb + 1*GMAT + d1, gW0 + s1);
        if (NW == 2) {
            cp16(sb + 2*GMAT + d0, gW1 + s0);
            cp16(sb + 2*GMAT + d1, gW1 + s1);
        }
    };

    issue(0, 0);
    cp_commit();

    const int a_r = wm0 + (lane & 15);
    const int a_c = (lane >> 4) * 8;
    const int b_r = wn0 + (lane & 7) + ((lane >> 4) << 3);
    const int b_c = ((lane >> 3) & 1) * 8;

    for (int c = 0; c < NCHUNK; c++) {
        const int s = c & 1;
        if (c + 1 < NCHUNK) { issue(c + 1, s ^ 1); cp_commit(); }
        if (c + 1 < NCHUNK) cp_wait<1>(); else cp_wait<0>();
        __syncthreads();

        const uint32_t sb = smem_base + s * STG;
        const uint32_t aB = sb, w0B = sb + GMAT, w1B = sb + 2*GMAT;

        #pragma unroll
        for (int kk = 0; kk < 2; kk++) {
            const int k16 = kk * 16;
            uint32_t b0[2][4], b1[2][4];
            #pragma unroll
            for (int jj = 0; jj < 2; jj++) {
                uint32_t off = (uint32_t)((b_r + jj*16) * (GSTRIDE*2) + (k16 + b_c) * 2);
                ldsm_x4(b0[jj], w0B + off);
                if (NW == 2) ldsm_x4(b1[jj], w1B + off);
            }
            #pragma unroll
            for (int i = 0; i < 4; i++) {
                uint32_t a[4];
                uint32_t off = (uint32_t)((a_r + i*16) * (GSTRIDE*2) + (k16 + a_c) * 2);
                ldsm_x4(a, aB + off);
                #pragma unroll
                for (int j = 0; j < 4; j++) {
                    mma_f16(acc[i][j], a, &b0[j >> 1][(j & 1) * 2]);
                    if (NW == 2) mma_f16(acc[i][j], a, &b1[j >> 1][(j & 1) * 2]);
                }
            }
        }
        __syncthreads();
    }

    // epilogue
    const int g = lane >> 2, t = lane & 3;
    #pragma unroll
    for (int j = 0; j < 4; j++) {
        const int col = n0 + wn0 + j*8 + t*2;
        const float bx = __ldg(&bias[col]);
        const float by = __ldg(&bias[col + 1]);
        #pragma unroll
        for (int i = 0; i < 4; i++) {
            const int r0 = m0 + wm0 + i*16 + g;
            float v0x = acc[i][j][0] + bx, v0y = acc[i][j][1] + by;
            float v1x = acc[i][j][2] + bx, v1y = acc[i][j][3] + by;
            if (F32OUT) {
                float2 w0, w1;
                w0.x = v0x; w0.y = v0y; w1.x = v1x; w1.y = v1y;
                *(float2*)&C[(size_t)r0 * Dq + col] = w0;
                *(float2*)&C[(size_t)(r0 + 8) * Dq + col] = w1;
            } else {
                *(__half2*)&H[(size_t)r0 * Dq + col] = __floats2half2_rn(v0x, v0y);
                *(__half2*)&H[(size_t)(r0+8) * Dq + col] = __floats2half2_rn(v1x, v1y);
            }
        }
    }
}

// ---------------------------------------------------------------------------
// FA2-style HMMA attention, fp16 internals, fp32 accum.
// 2-stage cp.async KV pipeline, Q fragments register-resident.
// ---------------------------------------------------------------------------
#define AST 72
#define AT_TILE  (64*AST*2)          // 9216 B per matrix
#define AT_STAGE (2*AT_TILE)         // 18432 B per stage (K+V)
#define QBYTES   (128*AST*2)         // 18432 B
#define KVOFF    QBYTES
#define AT_SMEM  (KVOFF + 2*AT_STAGE)  // 55296 B

__global__ __launch_bounds__(256, 2)
void attn_mma_kernel(const __half* __restrict__ Q16, const __half* __restrict__ K16,
                     const __half* __restrict__ V16, __half* __restrict__ A16)
{
    extern __shared__ char smem[];
    const uint32_t sbase = smem_to_u32(smem);
    const int tid = threadIdx.x, lane = tid & 31, wid = tid >> 5;
    const int bh = blockIdx.y, b = bh >> 4, h = bh & 15;
    const int q0 = blockIdx.x * 128;
    const int g = lane >> 2, t4 = lane & 3;

    // ---- stage Q (scaled by 1/8, exact in fp16) ----
    {
        __half* sQ = (__half*)smem;
        const int row = tid >> 1, halfo = (tid & 1) * 32;
        const __half2 sc = __floats2half2_rn(0.125f, 0.125f);
        size_t gq = ((size_t)(b*Sq) + q0 + row) * Dq + h*HDq + halfo;
        #pragma unroll
        for (int u = 0; u < 4; u++) {
            uint4 x4 = *(const uint4*)(Q16 + gq + u*8);
            __half2* p = (__half2*)&x4;
            #pragma unroll
            for (int e = 0; e < 4; e++) p[e] = __hmul2(p[e], sc);
            *(uint4*)&sQ[row*AST + halfo + u*8] = x4;
        }
    }

    // KV cp.async issue: each thread 4 x cp16 (2 per matrix)
    const int krow = tid >> 2, kd0 = (tid & 3) * 16;
    const size_t kvrowbase = (size_t)(b*Sq) * Dq + h*HDq + (size_t)krow * Dq + kd0;
    const uint32_t so = (uint32_t)((krow*AST + kd0) * 2);

    auto issue_kv = [&](int tile, int s) {
        size_t gk = kvrowbase + (size_t)tile * 64 * Dq;
        uint32_t sb = sbase + KVOFF + s * AT_STAGE;
        cp16(sb + 0*AT_TILE + so,      K16 + gk);
        cp16(sb + 0*AT_TILE + so + 16, K16 + gk + 8);
        cp16(sb + 1*AT_TILE + so,      V16 + gk);
        cp16(sb + 1*AT_TILE + so + 16, V16 + gk + 8);
    };

    issue_kv(0, 0); cp_commit();
    issue_kv(1, 1); cp_commit();
    __syncthreads();   // Q staged

    // Q fragments -> registers (16 regs)
    uint32_t qf[4][4];
    {
        uint32_t rowoff = (uint32_t)(((wid*16 + (lane & 15))*AST + (lane >> 4)*8) * 2);
        #pragma unroll
        for (int kk = 0; kk < 4; kk++)
            ldsm_x4(qf[kk], sbase + rowoff + kk*32);
    }

    float m0 = -1e30f, m1 = -1e30f, l0 = 0.f, l1 = 0.f;
    float o[8][4];
    #pragma unroll
    for (int j = 0; j < 8; j++)
        #pragma unroll
        for (int r = 0; r < 4; r++) o[j][r] = 0.f;

    const uint32_t kb_row = (lane & 7) + ((lane >> 4) & 1) * 8;
    const uint32_t kb_col = ((lane >> 3) & 1) * 8;
    const uint32_t vb_row = (lane & 7) + ((lane >> 3) & 1) * 8;
    const uint32_t vb_col = ((lane >> 4) & 1) * 8;

    for (int tile = 0; tile < Sq/64; tile++) {
        const int s = tile & 1;
        const uint32_t sb = sbase + KVOFF + s * AT_STAGE;
        const uint32_t oK = sb, oV = sb + AT_TILE;

        cp_wait<1>();
        __syncthreads();

        // ---- S = (Q/8) K^T ----
        float sAcc[8][4];
        #pragma unroll
        for (int j = 0; j < 8; j++)
            #pragma unroll
            for (int r = 0; r < 4; r++) sAcc[j][r] = 0.f;
        #pragma unroll
        for (int kk = 0; kk < 4; kk++) {
            #pragma unroll
            for (int jj = 0; jj < 4; jj++) {
                uint32_t off = (uint32_t)(((jj*16 + kb_row)*AST + kk*16 + kb_col) * 2);
                uint32_t kf[4];
                ldsm_x4(kf, oK + off);
                mma_f16(sAcc[2*jj],   qf[kk], &kf[0]);
                mma_f16(sAcc[2*jj+1], qf[kk], &kf[2]);
            }
        }

        // ---- online softmax ----
        float mx0 = -1e30f, mx1 = -1e30f;
        #pragma unroll
        for (int j = 0; j < 8; j++) {
            mx0 = fmaxf(mx0, fmaxf(sAcc[j][0], sAcc[j][1]));
            mx1 = fmaxf(mx1, fmaxf(sAcc[j][2], sAcc[j][3]));
        }
        mx0 = fmaxf(mx0, __shfl_xor_sync(0xffffffffu, mx0, 1));
        mx0 = fmaxf(mx0, __shfl_xor_sync(0xffffffffu, mx0, 2));
        mx1 = fmaxf(mx1, __shfl_xor_sync(0xffffffffu, mx1, 1));
        mx1 = fmaxf(mx1, __shfl_xor_sync(0xffffffffu, mx1, 2));
        float mn0 = fmaxf(m0, mx0), mn1 = fmaxf(m1, mx1);
        float c0 = __expf(m0 - mn0), c1 = __expf(m1 - mn1);
        #pragma unroll
        for (int j = 0; j < 8; j++) {
            o[j][0] *= c0; o[j][1] *= c0;
            o[j][2] *= c1; o[j][3] *= c1;
        }
        float sum0 = 0.f, sum1 = 0.f;

        // ---- exp + pack + PV (interleaved per key-block) ----
        #pragma unroll
        for (int kk = 0; kk < 4; kk++) {
            float* s0 = sAcc[2*kk];
            float* s1 = sAcc[2*kk+1];
            s0[0] = __expf(s0[0] - mn0); sum0 += s0[0];
            s0[1] = __expf(s0[1] - mn0); sum0 += s0[1];
            s0[2] = __expf(s0[2] - mn1); sum1 += s0[2];
            s0[3] = __expf(s0[3] - mn1); sum1 += s0[3];
            s1[0] = __expf(s1[0] - mn0); sum0 += s1[0];
            s1[1] = __expf(s1[1] - mn0); sum0 += s1[1];
            s1[2] = __expf(s1[2] - mn1); sum1 += s1[2];
            s1[3] = __expf(s1[3] - mn1); sum1 += s1[3];

            uint32_t pf[4];
            pf[0] = pack_h16(s0[0], s0[1]);
            pf[1] = pack_h16(s0[2], s0[3]);
            pf[2] = pack_h16(s1[0], s1[1]);
            pf[3] = pack_h16(s1[2], s1[3]);

            #pragma unroll
            for (int jj = 0; jj < 4; jj++) {
                uint32_t off = (uint32_t)(((kk*16 + vb_row)*AST + jj*16 + vb_col) * 2);
                uint32_t vf[4];
                ldsm_x4_trans(vf, oV + off);
                mma_f16(o[2*jj],   pf, &vf[0]);
                mma_f16(o[2*jj+1], pf, &vf[2]);
            }
        }

        sum0 += __shfl_xor_sync(0xffffffffu, sum0, 1);
        sum0 += __shfl_xor_sync(0xffffffffu, sum0, 2);
        sum1 += __shfl_xor_sync(0xffffffffu, sum1, 1);
        sum1 += __shfl_xor_sync(0xffffffffu, sum1, 2);
        m0 = mn0; m1 = mn1;
        l0 = l0 * c0 + sum0;
        l1 = l1 * c1 + sum1;

        __syncthreads();
        if (tile + 2 < Sq/64) { issue_kv(tile + 2, s); cp_commit(); }
    }

    // ---- epilogue: normalize, write fp16 ----
    float inv0 = 1.0f / l0, inv1 = 1.0f / l1;
    const int row0 = q0 + wid*16 + g;
    size_t ob0 = ((size_t)(b*Sq) + row0) * Dq + h*HDq;
    size_t ob1 = ob0 + (size_t)8 * Dq;
    #pragma unroll
    for (int j = 0; j < 8; j++) {
        const int c = j*8 + t4*2;
        *(__half2*)&A16[ob0 + c] = __floats2half2_rn(o[j][0] * inv0, o[j][1] * inv0);
        *(__half2*)&A16[ob1 + c] = __floats2half2_rn(o[j][2] * inv1, o[j][3] * inv1);
    }
}

// ---------------------------------------------------------------------------
extern "C" void kernel_launch(void* const* d_in, const int* in_sizes, int n_in,
                              void* d_out, int out_size)
{
    const float* q   = (const float*)d_in[0];
    const float* k   = (const float*)d_in[1];
    const float* v   = (const float*)d_in[2];
    const float* w_q = (const float*)d_in[3];
    const float* b_q = (const float*)d_in[4];
    const float* w_k = (const float*)d_in[5];
    const float* b_k = (const float*)d_in[6];
    const float* w_v = (const float*)d_in[7];
    const float* b_v = (const float*)d_in[8];
    const float* w_fc= (const float*)d_in[9];
    const float* b_fc= (const float*)d_in[10];
    float* out = (float*)d_out;

    __half *x16, *w16h, *w16l, *wfc16, *Q16, *K16, *V16, *A16;
    cudaGetSymbolAddress((void**)&x16,  g_x16);
    cudaGetSymbolAddress((void**)&w16h, g_w16h);
    cudaGetSymbolAddress((void**)&w16l, g_w16l);
    cudaGetSymbolAddress((void**)&wfc16,g_wfc16);
    cudaGetSymbolAddress((void**)&Q16,  g_Q16);
    cudaGetSymbolAddress((void**)&K16,  g_K16);
    cudaGetSymbolAddress((void**)&V16,  g_V16);
    cudaGetSymbolAddress((void**)&A16,  g_A16);

    const int GS_QKV = 2 * 3 * GMAT;   // 61440
    const int GS_FC  = 2 * 2 * GMAT;   // 40960
    cudaFuncSetAttribute(gemm16_kernel<2,false>,
                         cudaFuncAttributeMaxDynamicSharedMemorySize, GS_QKV);
    cudaFuncSetAttribute(gemm16_kernel<1,true>,
                         cudaFuncAttributeMaxDynamicSharedMemorySize, GS_FC);
    cudaFuncSetAttribute(attn_mma_kernel,
                         cudaFuncAttributeMaxDynamicSharedMemorySize, AT_SMEM);

    const int actN4 = BSq*Dq/4;
    const int wN4   = DD/4;
    dim3 sblk(256);

    // weight splits/converts, one launch (z=0..2 hi/lo, z=3 fc single)
    split_w16<<<dim3((wN4 + 255)/256, 4), sblk>>>(
        (const float4*)w_q, (const float4*)w_k, (const float4*)w_v, (const float4*)w_fc,
        (__half2*)w16h, (__half2*)w16l, (__half2*)wfc16, wN4);

    // activation converts, one launch
    split_act16<<<dim3((actN4 + 255)/256, 3), sblk>>>(
        (const float4*)q, (const float4*)k, (const float4*)v, (__half2*)x16, actN4);

    // Q/K/V projections: A fp16 single x W fp16 hi/lo (2 terms) -> fp16
    gemm16_kernel<2,false><<<dim3(Dq/128, BSq/128, 3), 256, GS_QKV>>>(
        x16, w16h, w16l, b_q, b_k, b_v, nullptr, Q16, K16, V16);

    // attention (fp16 internals, fp32 accum) -> fp16
    attn_mma_kernel<<<dim3(Sq/128, Bq*Hq), 256, AT_SMEM>>>(Q16, K16, V16, A16);

    // fc projection: fp16 x fp16 single term -> fp32 out
    gemm16_kernel<1,true><<<dim3(Dq/128, BSq/128, 1), 256, GS_FC>>>(
        A16, wfc16, nullptr, b_fc, b_fc, b_fc, out, nullptr, nullptr, nullptr);
}